// round 2
// baseline (speedup 1.0000x reference)
#include <cuda_runtime.h>

// ConceptLayer: h = xW+b ; S = decayed prefix scan of h ; y = bilinear(h,S;C)+h ; LayerNorm
// Shapes: B=8 T=2048 E=512 H=16 D=32
#define Bn 8
#define Tn 2048
#define En 512
#define Hn 16
#define Dn 32
#define BT (Bn * Tn)          // 16384 tokens
#define LN_EPS 1e-3f
#define INV_DECAY (1.0f / 1.2f)
#define CHUNK 128             // scan chunk length
#define NCHUNK (Tn / CHUNK)   // 16
#define NCH (Bn * En)         // 4096 scan channels

// Scratch (allocation-free rule: __device__ globals)
__device__ float g_h[BT * En];        // projected hidden (B,T,E)
__device__ float g_S[BT * En];        // decayed prefix state (B,T,E)
__device__ float g_y[BT * En];        // pre-LN output
__device__ float g_local[NCHUNK * NCH];

// ---------------------------------------------------------------------------
// K1: h = x @ W + b.  M=16384 N=512 K=512. 128x128x8 tile, 8x8 per thread.
// ---------------------------------------------------------------------------
__global__ __launch_bounds__(256, 2) void gemm_bias_kernel(
    const float* __restrict__ x, const float* __restrict__ W,
    const float* __restrict__ bias) {
    __shared__ float As[8][128];
    __shared__ float Bs[8][128];
    const int tid = threadIdx.x;
    const int bc = blockIdx.x;   // N/128 = 4
    const int br = blockIdx.y;   // M/128 = 128
    const int tx = tid & 15, ty = tid >> 4;

    float acc[8][8];
#pragma unroll
    for (int r = 0; r < 8; ++r)
#pragma unroll
        for (int c = 0; c < 8; ++c) acc[r][c] = 0.f;

    const int a_m = tid >> 1;        // 0..127
    const int a_k = (tid & 1) * 4;   // 0 or 4
    const int b_k = tid >> 5;        // 0..7
    const int b_n = (tid & 31) * 4;  // 0..124
    const float* xg = x + (br * 128 + a_m) * 512 + a_k;
    const float* wg = W + b_k * 512 + bc * 128 + b_n;

    for (int kt = 0; kt < 64; ++kt) {
        float4 av = *reinterpret_cast<const float4*>(xg + kt * 8);
        float4 bv = *reinterpret_cast<const float4*>(wg + kt * 8 * 512);
        __syncthreads();
        As[a_k + 0][a_m] = av.x;
        As[a_k + 1][a_m] = av.y;
        As[a_k + 2][a_m] = av.z;
        As[a_k + 3][a_m] = av.w;
        *reinterpret_cast<float4*>(&Bs[b_k][b_n]) = bv;
        __syncthreads();
#pragma unroll
        for (int kk = 0; kk < 8; ++kk) {
            float a[8], bb[8];
#pragma unroll
            for (int r = 0; r < 8; ++r) a[r] = As[kk][ty * 8 + r];
#pragma unroll
            for (int c = 0; c < 8; ++c) bb[c] = Bs[kk][tx * 8 + c];
#pragma unroll
            for (int r = 0; r < 8; ++r)
#pragma unroll
                for (int c = 0; c < 8; ++c) acc[r][c] = fmaf(a[r], bb[c], acc[r][c]);
        }
    }
#pragma unroll
    for (int r = 0; r < 8; ++r) {
        const int m = br * 128 + ty * 8 + r;
#pragma unroll
        for (int c = 0; c < 8; c += 4) {
            const int n = bc * 128 + tx * 8 + c;
            float4 o;
            o.x = acc[r][c + 0] + bias[n + 0];
            o.y = acc[r][c + 1] + bias[n + 1];
            o.z = acc[r][c + 2] + bias[n + 2];
            o.w = acc[r][c + 3] + bias[n + 3];
            *reinterpret_cast<float4*>(&g_h[m * 512 + n]) = o;
        }
    }
}

// ---------------------------------------------------------------------------
// K2a: per-chunk local scan value (recurrence started from 0)
// s_{t+1} = (s_t + h_t)/1.2 is linear -> chunk carry composes as s0*r^L + local
// ---------------------------------------------------------------------------
__global__ void scan_local_kernel() {
    const int tid = blockIdx.x * blockDim.x + threadIdx.x;  // 65536
    const int m = tid >> 12;       // chunk
    const int c = tid & 4095;      // channel = b*512 + hd
    const int b = c >> 9, hd = c & 511;
    const float* hp = g_h + (b * Tn + m * CHUNK) * En + hd;
    float s = 0.f;
#pragma unroll 4
    for (int t = 0; t < CHUNK; ++t) s = (s + hp[t * En]) * INV_DECAY;
    g_local[m * NCH + c] = s;
}

// ---------------------------------------------------------------------------
// K2b: combine chunk carries, emit S (value of state BEFORE consuming h_t)
// ---------------------------------------------------------------------------
__global__ void scan_emit_kernel() {
    const int tid = blockIdx.x * blockDim.x + threadIdx.x;
    const int m = tid >> 12;
    const int c = tid & 4095;
    const int b = c >> 9, hd = c & 511;
    float r = 1.f;
#pragma unroll
    for (int q = 0; q < CHUNK; ++q) r *= INV_DECAY;  // (1/1.2)^128
    float s = 0.f;
    for (int mm = 0; mm < m; ++mm) s = s * r + g_local[mm * NCH + c];
    const float* hp = g_h + (b * Tn + m * CHUNK) * En + hd;
    float* Sp = g_S + (b * Tn + m * CHUNK) * En + hd;
    for (int t = 0; t < CHUNK; ++t) {
        Sp[t * En] = s;
        s = (s + hp[t * En]) * INV_DECAY;
    }
}

// ---------------------------------------------------------------------------
// K3: bilinear + residual.
// y[bt, h*32+k] = h_k + sum_i h_i * (sum_j C[h,k,i,j] * S_j)
// Block: 64 tokens x 1 head, 8 warps; warp owns 4 k's; lane owns 2 tokens.
// C streams contiguously (j innermost), warp-uniform LDG.128, L2-resident.
// ---------------------------------------------------------------------------
__global__ __launch_bounds__(256, 2) void bilinear_kernel(const float* __restrict__ C) {
    __shared__ float hs[64][33];
    __shared__ float Ss[64][33];
    const int head = blockIdx.y;
    const int bt_base = blockIdx.x * 64;
    const int tid = threadIdx.x;

    for (int idx = tid; idx < 64 * 32; idx += 256) {
        const int rr = idx >> 5, i = idx & 31;
        const int bt = bt_base + rr;
        hs[rr][i] = g_h[bt * En + head * 32 + i];
        Ss[rr][i] = g_S[bt * En + head * 32 + i];
    }
    __syncthreads();

    const int lane = tid & 31, w = tid >> 5;
    const int tok0 = lane, tok1 = lane + 32;
    float S0[32], S1[32];
#pragma unroll
    for (int j = 0; j < 32; ++j) {
        S0[j] = Ss[tok0][j];
        S1[j] = Ss[tok1][j];
    }

#pragma unroll 1
    for (int kk = 0; kk < 4; ++kk) {
        const int k = w * 4 + kk;
        const float4* Cp =
            reinterpret_cast<const float4*>(C + (head * 32 + k) * 1024);
        float a0 = 0.f, a1 = 0.f;
#pragma unroll 4
        for (int i = 0; i < 32; ++i) {
            float v0 = 0.f, v1 = 0.f;
#pragma unroll
            for (int j4 = 0; j4 < 8; ++j4) {
                const float4 cv = __ldg(&Cp[i * 8 + j4]);
                v0 = fmaf(cv.x, S0[j4 * 4 + 0], v0);
                v1 = fmaf(cv.x, S1[j4 * 4 + 0], v1);
                v0 = fmaf(cv.y, S0[j4 * 4 + 1], v0);
                v1 = fmaf(cv.y, S1[j4 * 4 + 1], v1);
                v0 = fmaf(cv.z, S0[j4 * 4 + 2], v0);
                v1 = fmaf(cv.z, S1[j4 * 4 + 2], v1);
                v0 = fmaf(cv.w, S0[j4 * 4 + 3], v0);
                v1 = fmaf(cv.w, S1[j4 * 4 + 3], v1);
            }
            a0 = fmaf(hs[tok0][i], v0, a0);
            a1 = fmaf(hs[tok1][i], v1, a1);
        }
        const int col = head * 32 + k;
        g_y[(bt_base + tok0) * En + col] = a0 + hs[tok0][k];
        g_y[(bt_base + tok1) * En + col] = a1 + hs[tok1][k];
    }
}

// ---------------------------------------------------------------------------
// K4: LayerNorm over E=512 (population variance, eps=1e-3), warp per token.
// ---------------------------------------------------------------------------
__global__ __launch_bounds__(256) void ln_kernel(const float* __restrict__ gamma,
                                                 const float* __restrict__ beta,
                                                 float* __restrict__ out) {
    const int w = threadIdx.x >> 5, lane = threadIdx.x & 31;
    const int token = blockIdx.x * 8 + w;
    const float* yp = g_y + token * En;
    float vals[16];
    float sum = 0.f, sq = 0.f;
#pragma unroll
    for (int c2 = 0; c2 < 16; ++c2) {
        const float v = yp[c2 * 32 + lane];
        vals[c2] = v;
        sum += v;
        sq = fmaf(v, v, sq);
    }
#pragma unroll
    for (int o = 16; o; o >>= 1) {
        sum += __shfl_xor_sync(0xffffffffu, sum, o);
        sq += __shfl_xor_sync(0xffffffffu, sq, o);
    }
    const float mu = sum * (1.f / 512.f);
    const float var = sq * (1.f / 512.f) - mu * mu;
    const float inv = rsqrtf(var + LN_EPS);
    float* op = out + token * En;
#pragma unroll
    for (int c2 = 0; c2 < 16; ++c2) {
        const int e = c2 * 32 + lane;
        op[e] = (vals[c2] - mu) * inv * gamma[e] + beta[e];
    }
}

// ---------------------------------------------------------------------------
extern "C" void kernel_launch(void* const* d_in, const int* in_sizes, int n_in,
                              void* d_out, int out_size) {
    const float* x = (const float*)d_in[0];
    const float* W = (const float*)d_in[1];
    const float* bias = (const float*)d_in[2];
    const float* cmap = (const float*)d_in[3];
    const float* gamma = (const float*)d_in[4];
    const float* beta = (const float*)d_in[5];
    float* out = (float*)d_out;

    gemm_bias_kernel<<<dim3(4, 128), 256>>>(x, W, bias);
    scan_local_kernel<<<NCHUNK * NCH / 256, 256>>>();
    scan_emit_kernel<<<NCHUNK * NCH / 256, 256>>>();
    bilinear_kernel<<<dim3(BT / 64, Hn), 256>>>(cmap);
    ln_kernel<<<BT / 8, 256>>>(gamma, beta, out);
}

// round 4
// speedup vs baseline: 1.7165x; 1.7165x over previous
#include <cuda_runtime.h>
#include <cuda_bf16.h>
#include <cstdint>

// ConceptLayer: h = xW+b ; S = decayed scan ; y = bilinear(h,S;C)+h ; LayerNorm
// B=8 T=2048 E=512 H=16 D=32.  sm_100-safe: mma.sync (HMMA), cp.async, ldmatrix.
#define Bn 8
#define Tn 2048
#define En 512
#define Hn 16
#define BT (Bn * Tn)
#define LN_EPS 1e-3f
#define INV_DECAY (1.0f / 1.2f)
#define CHUNK 128
#define NCHUNK (Tn / CHUNK)
#define NCH (Bn * En)

__device__ float g_h[BT * En];
__device__ float g_S[BT * En];
__device__ float g_y[BT * En];
__device__ float g_local[NCHUNK * NCH];
// C packed split-bf16: [head][n=k*32+i][72 bf16] = [Ch(j 0..31) | Cl(j 0..31) | pad8]
// stored as 9 uint4 (144B) per row.
__device__ uint4 g_Cpack[Hn * 1024 * 9];

__device__ __forceinline__ unsigned short bf_hi(float v, float& rem) {
    __nv_bfloat16 h = __float2bfloat16(v);
    rem = v - __bfloat162float(h);
    return __bfloat16_as_ushort(h);
}
__device__ __forceinline__ uint32_t smem_u32(const void* p) {
    uint32_t a;
    asm("{ .reg .u64 t; cvta.to.shared.u64 t, %1; cvt.u32.u64 %0, t; }" : "=r"(a) : "l"(p));
    return a;
}
__device__ __forceinline__ void mma16816(float* d, const uint32_t* a, uint32_t b0, uint32_t b1) {
    asm volatile(
        "mma.sync.aligned.m16n8k16.row.col.f32.bf16.bf16.f32 "
        "{%0,%1,%2,%3}, {%4,%5,%6,%7}, {%8,%9}, {%0,%1,%2,%3};"
        : "+f"(d[0]), "+f"(d[1]), "+f"(d[2]), "+f"(d[3])
        : "r"(a[0]), "r"(a[1]), "r"(a[2]), "r"(a[3]), "r"(b0), "r"(b1));
}
__device__ __forceinline__ void ldsm_x2(uint32_t& r0, uint32_t& r1, uint32_t addr) {
    asm volatile("ldmatrix.sync.aligned.m8n8.x2.shared.b16 {%0,%1}, [%2];"
                 : "=r"(r0), "=r"(r1) : "r"(addr));
}
__device__ __forceinline__ void cp_async16(uint32_t dst, const void* src) {
    asm volatile("cp.async.cg.shared.global [%0], [%1], 16;" :: "r"(dst), "l"(src) : "memory");
}

// ---------------------------------------------------------------------------
// K0: pack C -> split bf16 [head][n][72]
// ---------------------------------------------------------------------------
__global__ void cpack_kernel(const float* __restrict__ C) {
    const int idx = blockIdx.x * 256 + threadIdx.x;  // 16384 rows
    const int head = idx >> 10, n = idx & 1023;
    const float* src = C + (size_t)(head * 1024 + n) * 32;  // [h][k][i][j], n=k*32+i
    unsigned short hi[32], lo[32];
#pragma unroll
    for (int j = 0; j < 32; ++j) {
        float r;
        hi[j] = bf_hi(src[j], r);
        lo[j] = __bfloat16_as_ushort(__float2bfloat16(r));
    }
    uint4* dst = g_Cpack + (size_t)idx * 9;
#pragma unroll
    for (int q = 0; q < 4; ++q) {
        uint4 v;
        v.x = (uint32_t)hi[q * 8 + 0] | ((uint32_t)hi[q * 8 + 1] << 16);
        v.y = (uint32_t)hi[q * 8 + 2] | ((uint32_t)hi[q * 8 + 3] << 16);
        v.z = (uint32_t)hi[q * 8 + 4] | ((uint32_t)hi[q * 8 + 5] << 16);
        v.w = (uint32_t)hi[q * 8 + 6] | ((uint32_t)hi[q * 8 + 7] << 16);
        dst[q] = v;
        uint4 w;
        w.x = (uint32_t)lo[q * 8 + 0] | ((uint32_t)lo[q * 8 + 1] << 16);
        w.y = (uint32_t)lo[q * 8 + 2] | ((uint32_t)lo[q * 8 + 3] << 16);
        w.z = (uint32_t)lo[q * 8 + 4] | ((uint32_t)lo[q * 8 + 5] << 16);
        w.w = (uint32_t)lo[q * 8 + 6] | ((uint32_t)lo[q * 8 + 7] << 16);
        dst[4 + q] = w;
    }
}

// ---------------------------------------------------------------------------
// K1: h = x @ W + b (fp32 CUDA-core; next round's tensor target)
// ---------------------------------------------------------------------------
__global__ __launch_bounds__(256, 2) void gemm_bias_kernel(
    const float* __restrict__ x, const float* __restrict__ W,
    const float* __restrict__ bias) {
    __shared__ float As[8][128];
    __shared__ float Bs[8][128];
    const int tid = threadIdx.x;
    const int bc = blockIdx.x, br = blockIdx.y;
    const int tx = tid & 15, ty = tid >> 4;
    float acc[8][8];
#pragma unroll
    for (int r = 0; r < 8; ++r)
#pragma unroll
        for (int c = 0; c < 8; ++c) acc[r][c] = 0.f;
    const int a_m = tid >> 1, a_k = (tid & 1) * 4;
    const int b_k = tid >> 5, b_n = (tid & 31) * 4;
    const float* xg = x + (br * 128 + a_m) * 512 + a_k;
    const float* wg = W + b_k * 512 + bc * 128 + b_n;
    for (int kt = 0; kt < 64; ++kt) {
        float4 av = *reinterpret_cast<const float4*>(xg + kt * 8);
        float4 bv = *reinterpret_cast<const float4*>(wg + kt * 8 * 512);
        __syncthreads();
        As[a_k + 0][a_m] = av.x; As[a_k + 1][a_m] = av.y;
        As[a_k + 2][a_m] = av.z; As[a_k + 3][a_m] = av.w;
        *reinterpret_cast<float4*>(&Bs[b_k][b_n]) = bv;
        __syncthreads();
#pragma unroll
        for (int kk = 0; kk < 8; ++kk) {
            float a[8], bb[8];
#pragma unroll
            for (int r = 0; r < 8; ++r) a[r] = As[kk][ty * 8 + r];
#pragma unroll
            for (int c = 0; c < 8; ++c) bb[c] = Bs[kk][tx * 8 + c];
#pragma unroll
            for (int r = 0; r < 8; ++r)
#pragma unroll
                for (int c = 0; c < 8; ++c) acc[r][c] = fmaf(a[r], bb[c], acc[r][c]);
        }
    }
#pragma unroll
    for (int r = 0; r < 8; ++r) {
        const int m = br * 128 + ty * 8 + r;
#pragma unroll
        for (int c = 0; c < 8; c += 4) {
            const int n = bc * 128 + tx * 8 + c;
            float4 o;
            o.x = acc[r][c + 0] + bias[n + 0];
            o.y = acc[r][c + 1] + bias[n + 1];
            o.z = acc[r][c + 2] + bias[n + 2];
            o.w = acc[r][c + 3] + bias[n + 3];
            *reinterpret_cast<float4*>(&g_h[m * 512 + n]) = o;
        }
    }
}

// ---------------------------------------------------------------------------
// K2: decayed scan (chunked linear recurrence)
// ---------------------------------------------------------------------------
__global__ void scan_local_kernel() {
    const int tid = blockIdx.x * blockDim.x + threadIdx.x;
    const int m = tid >> 12, c = tid & 4095;
    const int b = c >> 9, hd = c & 511;
    const float* hp = g_h + (b * Tn + m * CHUNK) * En + hd;
    float s = 0.f;
#pragma unroll 4
    for (int t = 0; t < CHUNK; ++t) s = (s + hp[t * En]) * INV_DECAY;
    g_local[m * NCH + c] = s;
}
__global__ void scan_emit_kernel() {
    const int tid = blockIdx.x * blockDim.x + threadIdx.x;
    const int m = tid >> 12, c = tid & 4095;
    const int b = c >> 9, hd = c & 511;
    float r = 1.f;
#pragma unroll
    for (int q = 0; q < CHUNK; ++q) r *= INV_DECAY;
    float s = 0.f;
    for (int mm = 0; mm < m; ++mm) s = s * r + g_local[mm * NCH + c];
    const float* hp = g_h + (b * Tn + m * CHUNK) * En + hd;
    float* Sp = g_S + (b * Tn + m * CHUNK) * En + hd;
    for (int t = 0; t < CHUNK; ++t) {
        Sp[t * En] = s;
        s = (s + hp[t * En]) * INV_DECAY;
    }
}

// ---------------------------------------------------------------------------
// K3: bilinear via mma.sync bf16 split.
// Block = (128 tokens, head). A = S' [128][72] (Sh|Sl), B = C' smem [1024][72],
// 4 compute warps x 2 m-tiles; P stays in fragments; epilogue y = P.h + h.
// ---------------------------------------------------------------------------
#define SM_A 0            // 128*144 = 18432
#define SM_B 18432        // 1024*144 = 147456
#define SM_H 165888       // 128*160 = 20480 (pitch 40 f32)
#define SM_Y 186368       // 128*33*4 = 16896
#define SM_TOTAL 203264

__global__ __launch_bounds__(256, 1) void bilinear_mma_kernel() {
    extern __shared__ char smem[];
    const uint32_t sb = smem_u32(smem);
    const int tid = threadIdx.x;
    const int wid = tid >> 5, lane = tid & 31;
    const int head = blockIdx.y;
    const int tile = blockIdx.x;
    float* hs = reinterpret_cast<float*>(smem + SM_H);
    float* ys = reinterpret_cast<float*>(smem + SM_Y);

    // ---- prep: A pack (threads 0-127), h copy (threads 128-255), C cp.async (all)
    if (tid < 128) {
        const int r = tid;
        const float* Sp = &g_S[(size_t)(tile * 128 + r) * 512 + head * 32];
        unsigned short sh[32], sl[32];
#pragma unroll
        for (int q = 0; q < 8; ++q) {
            float4 v = *reinterpret_cast<const float4*>(Sp + q * 4);
            float r0, r1, r2, r3;
            sh[q * 4 + 0] = bf_hi(v.x, r0); sh[q * 4 + 1] = bf_hi(v.y, r1);
            sh[q * 4 + 2] = bf_hi(v.z, r2); sh[q * 4 + 3] = bf_hi(v.w, r3);
            sl[q * 4 + 0] = __bfloat16_as_ushort(__float2bfloat16(r0));
            sl[q * 4 + 1] = __bfloat16_as_ushort(__float2bfloat16(r1));
            sl[q * 4 + 2] = __bfloat16_as_ushort(__float2bfloat16(r2));
            sl[q * 4 + 3] = __bfloat16_as_ushort(__float2bfloat16(r3));
        }
        uint4* arow = reinterpret_cast<uint4*>(smem + SM_A + r * 144);
#pragma unroll
        for (int q = 0; q < 4; ++q) {
            uint4 v;
            v.x = (uint32_t)sh[q * 8 + 0] | ((uint32_t)sh[q * 8 + 1] << 16);
            v.y = (uint32_t)sh[q * 8 + 2] | ((uint32_t)sh[q * 8 + 3] << 16);
            v.z = (uint32_t)sh[q * 8 + 4] | ((uint32_t)sh[q * 8 + 5] << 16);
            v.w = (uint32_t)sh[q * 8 + 6] | ((uint32_t)sh[q * 8 + 7] << 16);
            arow[q] = v;
            uint4 w;
            w.x = (uint32_t)sl[q * 8 + 0] | ((uint32_t)sl[q * 8 + 1] << 16);
            w.y = (uint32_t)sl[q * 8 + 2] | ((uint32_t)sl[q * 8 + 3] << 16);
            w.z = (uint32_t)sl[q * 8 + 4] | ((uint32_t)sl[q * 8 + 5] << 16);
            w.w = (uint32_t)sl[q * 8 + 6] | ((uint32_t)sl[q * 8 + 7] << 16);
            arow[4 + q] = w;
        }
    } else {
        const int r = tid - 128;
        const float4* hp = reinterpret_cast<const float4*>(
            &g_h[(size_t)(tile * 128 + r) * 512 + head * 32]);
        float4* hrow = reinterpret_cast<float4*>(&hs[r * 40]);
#pragma unroll
        for (int q = 0; q < 8; ++q) hrow[q] = hp[q];
    }
    {
        const uint4* gsrc = g_Cpack + (size_t)head * 9216;
#pragma unroll
        for (int t = 0; t < 36; ++t) {
            const int gidx = tid + t * 256;
            cp_async16(sb + SM_B + gidx * 16, gsrc + gidx);
        }
        asm volatile("cp.async.commit_group;" ::: "memory");
        asm volatile("cp.async.wait_group 0;" ::: "memory");
    }
    __syncthreads();

    if (wid < 4) {
        const int g = lane >> 2, tg = lane & 3;
        const int m0a = wid * 32, m0b = wid * 32 + 16;
        // A fragments: [mtile][s=0..3][4 regs]; col block s*16, rows g/g+8
        uint32_t afr[2][4][4];
#pragma unroll
        for (int m = 0; m < 2; ++m) {
            const int mr = (m ? m0b : m0a);
#pragma unroll
            for (int s = 0; s < 4; ++s) {
                const char* base = smem + SM_A;
                afr[m][s][0] = *reinterpret_cast<const uint32_t*>(base + (mr + g) * 144 + (s * 16 + tg * 2) * 2);
                afr[m][s][1] = *reinterpret_cast<const uint32_t*>(base + (mr + g + 8) * 144 + (s * 16 + tg * 2) * 2);
                afr[m][s][2] = *reinterpret_cast<const uint32_t*>(base + (mr + g) * 144 + (s * 16 + 8 + tg * 2) * 2);
                afr[m][s][3] = *reinterpret_cast<const uint32_t*>(base + (mr + g + 8) * 144 + (s * 16 + 8 + tg * 2) * 2);
            }
        }
        // h registers: [mtile][itile][4] = h(g,i0),h(g,i0+1),h(g+8,i0),h(g+8,i0+1)
        float hreg[2][4][4];
#pragma unroll
        for (int m = 0; m < 2; ++m) {
            const int mr = (m ? m0b : m0a);
#pragma unroll
            for (int it = 0; it < 4; ++it) {
                const int i0 = it * 8 + tg * 2;
                hreg[m][it][0] = hs[(mr + g) * 40 + i0];
                hreg[m][it][1] = hs[(mr + g) * 40 + i0 + 1];
                hreg[m][it][2] = hs[(mr + g + 8) * 40 + i0];
                hreg[m][it][3] = hs[(mr + g + 8) * 40 + i0 + 1];
            }
        }
        // ldmatrix base address (lanes 0-15 used)
        const uint32_t bbase = sb + SM_B + (lane & 7) * 144 + ((lane >> 3) & 1) * 16;

        for (int k = 0; k < 32; ++k) {
            float yA0 = 0.f, yB0 = 0.f, yA1 = 0.f, yB1 = 0.f;
#pragma unroll
            for (int it = 0; it < 4; ++it) {
                const uint32_t boff = bbase + (uint32_t)(k * 32 + it * 8) * 144;
                uint32_t bh0a, bh0b, bh1a, bh1b, bl0a, bl0b, bl1a, bl1b;
                ldsm_x2(bh0a, bh0b, boff);        // Ch j0-15
                ldsm_x2(bh1a, bh1b, boff + 32);   // Ch j16-31
                ldsm_x2(bl0a, bl0b, boff + 64);   // Cl j0-15
                ldsm_x2(bl1a, bl1b, boff + 96);   // Cl j16-31
#pragma unroll
                for (int m = 0; m < 2; ++m) {
                    float d[4] = {0.f, 0.f, 0.f, 0.f};
                    mma16816(d, afr[m][0], bh0a, bh0b);  // Sh.Ch
                    mma16816(d, afr[m][1], bh1a, bh1b);
                    mma16816(d, afr[m][2], bh0a, bh0b);  // Sl.Ch
                    mma16816(d, afr[m][3], bh1a, bh1b);
                    mma16816(d, afr[m][0], bl0a, bl0b);  // Sh.Cl
                    mma16816(d, afr[m][1], bl1a, bl1b);
                    if (m == 0) {
                        yA0 = fmaf(d[0], hreg[0][it][0], fmaf(d[1], hreg[0][it][1], yA0));
                        yB0 = fmaf(d[2], hreg[0][it][2], fmaf(d[3], hreg[0][it][3], yB0));
                    } else {
                        yA1 = fmaf(d[0], hreg[1][it][0], fmaf(d[1], hreg[1][it][1], yA1));
                        yB1 = fmaf(d[2], hreg[1][it][2], fmaf(d[3], hreg[1][it][3], yB1));
                    }
                }
            }
            // quad reduce (lanes tg=0..3 share same row g)
#pragma unroll
            for (int o = 1; o <= 2; o <<= 1) {
                yA0 += __shfl_xor_sync(0xffffffffu, yA0, o);
                yB0 += __shfl_xor_sync(0xffffffffu, yB0, o);
                yA1 += __shfl_xor_sync(0xffffffffu, yA1, o);
                yB1 += __shfl_xor_sync(0xffffffffu, yB1, o);
            }
            if (tg == (k & 3)) {
                ys[(m0a + g) * 33 + k] = yA0;
                ys[(m0a + g + 8) * 33 + k] = yB0;
                ys[(m0b + g) * 33 + k] = yA1;
                ys[(m0b + g + 8) * 33 + k] = yB1;
            }
        }
    }
    __syncthreads();

    // residual + coalesced store
#pragma unroll
    for (int p = 0; p < 4; ++p) {
        const int idx = tid + p * 256;
        const int r = idx >> 3, c = (idx & 7) * 4;
        float4 v;
        v.x = ys[r * 33 + c + 0] + hs[r * 40 + c + 0];
        v.y = ys[r * 33 + c + 1] + hs[r * 40 + c + 1];
        v.z = ys[r * 33 + c + 2] + hs[r * 40 + c + 2];
        v.w = ys[r * 33 + c + 3] + hs[r * 40 + c + 3];
        *reinterpret_cast<float4*>(
            &g_y[(size_t)(tile * 128 + r) * 512 + head * 32 + c]) = v;
    }
}

// ---------------------------------------------------------------------------
// K4: LayerNorm
// ---------------------------------------------------------------------------
__global__ __launch_bounds__(256) void ln_kernel(const float* __restrict__ gamma,
                                                 const float* __restrict__ beta,
                                                 float* __restrict__ out) {
    const int w = threadIdx.x >> 5, lane = threadIdx.x & 31;
    const int token = blockIdx.x * 8 + w;
    const float* yp = g_y + (size_t)token * En;
    float vals[16], sum = 0.f, sq = 0.f;
#pragma unroll
    for (int c2 = 0; c2 < 16; ++c2) {
        const float v = yp[c2 * 32 + lane];
        vals[c2] = v; sum += v; sq = fmaf(v, v, sq);
    }
#pragma unroll
    for (int o = 16; o; o >>= 1) {
        sum += __shfl_xor_sync(0xffffffffu, sum, o);
        sq += __shfl_xor_sync(0xffffffffu, sq, o);
    }
    const float mu = sum * (1.f / 512.f);
    const float var = sq * (1.f / 512.f) - mu * mu;
    const float inv = rsqrtf(var + LN_EPS);
    float* op = out + (size_t)token * En;
#pragma unroll
    for (int c2 = 0; c2 < 16; ++c2) {
        const int e = c2 * 32 + lane;
        op[e] = (vals[c2] - mu) * inv * gamma[e] + beta[e];
    }
}

// ---------------------------------------------------------------------------
extern "C" void kernel_launch(void* const* d_in, const int* in_sizes, int n_in,
                              void* d_out, int out_size) {
    const float* x = (const float*)d_in[0];
    const float* W = (const float*)d_in[1];
    const float* bias = (const float*)d_in[2];
    const float* cmap = (const float*)d_in[3];
    const float* gamma = (const float*)d_in[4];
    const float* beta = (const float*)d_in[5];
    float* out = (float*)d_out;

    static int smem_set = 0;
    if (!smem_set) {
        cudaFuncSetAttribute(bilinear_mma_kernel,
                             cudaFuncAttributeMaxDynamicSharedMemorySize, SM_TOTAL);
        smem_set = 1;
    }

    cpack_kernel<<<64, 256>>>(cmap);
    gemm_bias_kernel<<<dim3(4, 128), 256>>>(x, W, bias);
    scan_local_kernel<<<NCHUNK * NCH / 256, 256>>>();
    scan_emit_kernel<<<NCHUNK * NCH / 256, 256>>>();
    bilinear_mma_kernel<<<dim3(128, Hn), 256, SM_TOTAL>>>();
    ln_kernel<<<BT / 8, 256>>>(gamma, beta, out);
}

// round 5
// speedup vs baseline: 2.3891x; 1.3918x over previous
#include <cuda_runtime.h>
#include <cuda_bf16.h>
#include <cstdint>

// ConceptLayer: h = xW+b ; S = decayed scan ; y = bilinear(h,S;C)+h ; LayerNorm
// B=8 T=2048 E=512 H=16 D=32.  sm_100-safe: mma.sync (HMMA), cp.async, ldmatrix.
#define Bn 8
#define Tn 2048
#define En 512
#define Hn 16
#define BT (Bn * Tn)
#define LN_EPS 1e-3f
#define INV_DECAY (1.0f / 1.2f)
#define CHUNK 128
#define NCHUNK (Tn / CHUNK)
#define NCH (Bn * En)
#define WPITCH 520   // bf16 elements per row of packed W (1040B, 16B-skewed banks)

__device__ float g_h[BT * En];
__device__ float g_S[BT * En];
__device__ float g_y[BT * En];
__device__ float g_local[NCHUNK * NCH];
// C packed split-bf16: [head][n=k*32+i][72 bf16] = [Ch | Cl | pad]
__device__ uint4 g_Cpack[Hn * 1024 * 9];
// W packed transposed split-bf16: [n][k] pitch 520
__device__ __nv_bfloat16 g_Wh[512 * WPITCH];
__device__ __nv_bfloat16 g_Wl[512 * WPITCH];

__device__ __forceinline__ unsigned short bf_hi(float v, float& rem) {
    __nv_bfloat16 h = __float2bfloat16(v);
    rem = v - __bfloat162float(h);
    return __bfloat16_as_ushort(h);
}
__device__ __forceinline__ uint32_t smem_u32(const void* p) {
    uint32_t a;
    asm("{ .reg .u64 t; cvta.to.shared.u64 t, %1; cvt.u32.u64 %0, t; }" : "=r"(a) : "l"(p));
    return a;
}
__device__ __forceinline__ void mma16816(float* d, const uint32_t* a, uint32_t b0, uint32_t b1) {
    asm volatile(
        "mma.sync.aligned.m16n8k16.row.col.f32.bf16.bf16.f32 "
        "{%0,%1,%2,%3}, {%4,%5,%6,%7}, {%8,%9}, {%0,%1,%2,%3};"
        : "+f"(d[0]), "+f"(d[1]), "+f"(d[2]), "+f"(d[3])
        : "r"(a[0]), "r"(a[1]), "r"(a[2]), "r"(a[3]), "r"(b0), "r"(b1));
}
__device__ __forceinline__ void ldsm_x2(uint32_t& r0, uint32_t& r1, uint32_t addr) {
    asm volatile("ldmatrix.sync.aligned.m8n8.x2.shared.b16 {%0,%1}, [%2];"
                 : "=r"(r0), "=r"(r1) : "r"(addr));
}
__device__ __forceinline__ void cp_async16(uint32_t dst, const void* src) {
    asm volatile("cp.async.cg.shared.global [%0], [%1], 16;" :: "r"(dst), "l"(src) : "memory");
}

// ---------------------------------------------------------------------------
// K0a: pack C -> split bf16 [head][n][72]
// ---------------------------------------------------------------------------
__global__ void cpack_kernel(const float* __restrict__ C) {
    const int idx = blockIdx.x * 256 + threadIdx.x;  // 16384 rows
    const float* src = C + (size_t)idx * 32;
    unsigned short hi[32], lo[32];
#pragma unroll
    for (int j = 0; j < 32; ++j) {
        float r;
        hi[j] = bf_hi(src[j], r);
        lo[j] = __bfloat16_as_ushort(__float2bfloat16(r));
    }
    uint4* dst = g_Cpack + (size_t)idx * 9;
#pragma unroll
    for (int q = 0; q < 4; ++q) {
        uint4 v;
        v.x = (uint32_t)hi[q * 8 + 0] | ((uint32_t)hi[q * 8 + 1] << 16);
        v.y = (uint32_t)hi[q * 8 + 2] | ((uint32_t)hi[q * 8 + 3] << 16);
        v.z = (uint32_t)hi[q * 8 + 4] | ((uint32_t)hi[q * 8 + 5] << 16);
        v.w = (uint32_t)hi[q * 8 + 6] | ((uint32_t)hi[q * 8 + 7] << 16);
        dst[q] = v;
        uint4 w;
        w.x = (uint32_t)lo[q * 8 + 0] | ((uint32_t)lo[q * 8 + 1] << 16);
        w.y = (uint32_t)lo[q * 8 + 2] | ((uint32_t)lo[q * 8 + 3] << 16);
        w.z = (uint32_t)lo[q * 8 + 4] | ((uint32_t)lo[q * 8 + 5] << 16);
        w.w = (uint32_t)lo[q * 8 + 6] | ((uint32_t)lo[q * 8 + 7] << 16);
        dst[4 + q] = w;
    }
}

// ---------------------------------------------------------------------------
// K0b: pack W [k][n] f32 -> g_Wh/g_Wl [n][k] bf16, pitch WPITCH
// ---------------------------------------------------------------------------
__global__ void wpack_kernel(const float* __restrict__ W) {
    const int n = (blockIdx.x & 1) * 256 + threadIdx.x;
    const int k0 = (blockIdx.x >> 1) * 8;   // 64 k-groups
    unsigned short hi[8], lo[8];
#pragma unroll
    for (int u = 0; u < 8; ++u) {
        float r;
        hi[u] = bf_hi(W[(size_t)(k0 + u) * 512 + n], r);
        lo[u] = __bfloat16_as_ushort(__float2bfloat16(r));
    }
    uint4 vh, vl;
    vh.x = (uint32_t)hi[0] | ((uint32_t)hi[1] << 16);
    vh.y = (uint32_t)hi[2] | ((uint32_t)hi[3] << 16);
    vh.z = (uint32_t)hi[4] | ((uint32_t)hi[5] << 16);
    vh.w = (uint32_t)hi[6] | ((uint32_t)hi[7] << 16);
    vl.x = (uint32_t)lo[0] | ((uint32_t)lo[1] << 16);
    vl.y = (uint32_t)lo[2] | ((uint32_t)lo[3] << 16);
    vl.z = (uint32_t)lo[4] | ((uint32_t)lo[5] << 16);
    vl.w = (uint32_t)lo[6] | ((uint32_t)lo[7] << 16);
    *reinterpret_cast<uint4*>(&g_Wh[(size_t)n * WPITCH + k0]) = vh;
    *reinterpret_cast<uint4*>(&g_Wl[(size_t)n * WPITCH + k0]) = vl;
}

// ---------------------------------------------------------------------------
// K1: h = x @ W + b via mma.sync bf16 split (xh.Wh + xl.Wh + xh.Wl).
// Block 128m x 128n, 8 warps (4m x 2n), K streamed in 8 chunks of 64.
// ---------------------------------------------------------------------------
#define G_AH 0
#define G_AL 18432
#define G_BH 36864
#define G_BL 55296
#define G_TOTAL 73728

__global__ __launch_bounds__(256, 2) void gemm_mma_kernel(
    const float* __restrict__ x, const float* __restrict__ bias) {
    extern __shared__ char smem[];
    const uint32_t sb = smem_u32(smem);
    const int tid = threadIdx.x;
    const int wid = tid >> 5, lane = tid & 31;
    const int g = lane >> 2, tg = lane & 3;
    const int mw = wid & 3, nw = wid >> 2;
    const int gm0 = blockIdx.y * 128;
    const int gn0 = blockIdx.x * 128;

    float acc[2][8][4];
#pragma unroll
    for (int mt = 0; mt < 2; ++mt)
#pragma unroll
        for (int nt = 0; nt < 8; ++nt)
#pragma unroll
            for (int e = 0; e < 4; ++e) acc[mt][nt][e] = 0.f;

    const int xm = tid >> 1, xh4 = (tid & 1) * 32;
    const uint32_t a_h_dst = sb + G_AH + xm * 144 + xh4 * 2;
    const uint32_t a_l_dst = sb + G_AL + xm * 144 + xh4 * 2;
    const int brow = tid >> 3, bseg = (tid & 7) * 8;

    for (int kc = 0; kc < 8; ++kc) {
        // W tiles via cp.async (each thread: 1 16B seg per row-group x 4 row-groups x2)
#pragma unroll
        for (int it = 0; it < 4; ++it) {
            const int row = brow + it * 32;
            cp_async16(sb + G_BH + row * 144 + bseg * 2,
                       &g_Wh[(size_t)(gn0 + row) * WPITCH + kc * 64 + bseg]);
            cp_async16(sb + G_BL + row * 144 + bseg * 2,
                       &g_Wl[(size_t)(gn0 + row) * WPITCH + kc * 64 + bseg]);
        }
        asm volatile("cp.async.commit_group;" ::: "memory");
        // x chunk -> split bf16 smem
        {
            const float4* xs = reinterpret_cast<const float4*>(
                x + (size_t)(gm0 + xm) * 512 + kc * 64 + xh4);
            unsigned short sh[32], sl[32];
#pragma unroll
            for (int q = 0; q < 8; ++q) {
                float4 v = xs[q];
                float r0, r1, r2, r3;
                sh[q * 4 + 0] = bf_hi(v.x, r0); sh[q * 4 + 1] = bf_hi(v.y, r1);
                sh[q * 4 + 2] = bf_hi(v.z, r2); sh[q * 4 + 3] = bf_hi(v.w, r3);
                sl[q * 4 + 0] = __bfloat16_as_ushort(__float2bfloat16(r0));
                sl[q * 4 + 1] = __bfloat16_as_ushort(__float2bfloat16(r1));
                sl[q * 4 + 2] = __bfloat16_as_ushort(__float2bfloat16(r2));
                sl[q * 4 + 3] = __bfloat16_as_ushort(__float2bfloat16(r3));
            }
#pragma unroll
            for (int q = 0; q < 4; ++q) {
                uint4 v;
                v.x = (uint32_t)sh[q * 8 + 0] | ((uint32_t)sh[q * 8 + 1] << 16);
                v.y = (uint32_t)sh[q * 8 + 2] | ((uint32_t)sh[q * 8 + 3] << 16);
                v.z = (uint32_t)sh[q * 8 + 4] | ((uint32_t)sh[q * 8 + 5] << 16);
                v.w = (uint32_t)sh[q * 8 + 6] | ((uint32_t)sh[q * 8 + 7] << 16);
                *reinterpret_cast<uint4*>(smem + (a_h_dst - sb) + q * 16) = v;
                uint4 w;
                w.x = (uint32_t)sl[q * 8 + 0] | ((uint32_t)sl[q * 8 + 1] << 16);
                w.y = (uint32_t)sl[q * 8 + 2] | ((uint32_t)sl[q * 8 + 3] << 16);
                w.z = (uint32_t)sl[q * 8 + 4] | ((uint32_t)sl[q * 8 + 5] << 16);
                w.w = (uint32_t)sl[q * 8 + 6] | ((uint32_t)sl[q * 8 + 7] << 16);
                *reinterpret_cast<uint4*>(smem + (a_l_dst - sb) + q * 16) = w;
            }
        }
        asm volatile("cp.async.wait_group 0;" ::: "memory");
        __syncthreads();

        const uint32_t bb = sb + (lane & 7) * 144 + ((lane >> 3) & 1) * 16 +
                            (nw * 64) * 144;
#pragma unroll
        for (int s = 0; s < 4; ++s) {
            uint32_t ah[2][4], al[2][4];
#pragma unroll
            for (int mt = 0; mt < 2; ++mt) {
                const int mr = mw * 32 + mt * 16;
                const uint32_t ra = (mr + g) * 144 + (s * 16 + tg * 2) * 2;
                const uint32_t rb = (mr + g + 8) * 144 + (s * 16 + tg * 2) * 2;
                ah[mt][0] = *reinterpret_cast<const uint32_t*>(smem + G_AH + ra);
                ah[mt][1] = *reinterpret_cast<const uint32_t*>(smem + G_AH + rb);
                ah[mt][2] = *reinterpret_cast<const uint32_t*>(smem + G_AH + ra + 16);
                ah[mt][3] = *reinterpret_cast<const uint32_t*>(smem + G_AH + rb + 16);
                al[mt][0] = *reinterpret_cast<const uint32_t*>(smem + G_AL + ra);
                al[mt][1] = *reinterpret_cast<const uint32_t*>(smem + G_AL + rb);
                al[mt][2] = *reinterpret_cast<const uint32_t*>(smem + G_AL + ra + 16);
                al[mt][3] = *reinterpret_cast<const uint32_t*>(smem + G_AL + rb + 16);
            }
#pragma unroll
            for (int nt = 0; nt < 8; ++nt) {
                uint32_t bh0, bh1, bl0, bl1;
                const uint32_t bo = bb + nt * 8 * 144 + s * 32;
                ldsm_x2(bh0, bh1, bo + G_BH);
                ldsm_x2(bl0, bl1, bo + G_BL);
#pragma unroll
                for (int mt = 0; mt < 2; ++mt) {
                    mma16816(acc[mt][nt], ah[mt], bh0, bh1);
                    mma16816(acc[mt][nt], al[mt], bh0, bh1);
                    mma16816(acc[mt][nt], ah[mt], bl0, bl1);
                }
            }
        }
        __syncthreads();
    }
    // epilogue: bias + store fp32
#pragma unroll
    for (int nt = 0; nt < 8; ++nt) {
        const int col = gn0 + nw * 64 + nt * 8 + tg * 2;
        const float b0 = __ldg(&bias[col]), b1 = __ldg(&bias[col + 1]);
#pragma unroll
        for (int mt = 0; mt < 2; ++mt) {
            const int row = gm0 + mw * 32 + mt * 16 + g;
            float2 v0 = {acc[mt][nt][0] + b0, acc[mt][nt][1] + b1};
            float2 v1 = {acc[mt][nt][2] + b0, acc[mt][nt][3] + b1};
            *reinterpret_cast<float2*>(&g_h[(size_t)row * 512 + col]) = v0;
            *reinterpret_cast<float2*>(&g_h[(size_t)(row + 8) * 512 + col]) = v1;
        }
    }
}

// ---------------------------------------------------------------------------
// K2: decayed scan — batched loads for MLP
// ---------------------------------------------------------------------------
__global__ void scan_local_kernel() {
    const int tid = blockIdx.x * blockDim.x + threadIdx.x;
    const int m = tid >> 12, c = tid & 4095;
    const int b = c >> 9, hd = c & 511;
    const float* hp = g_h + (size_t)(b * Tn + m * CHUNK) * En + hd;
    float s = 0.f;
    for (int t0 = 0; t0 < CHUNK; t0 += 8) {
        float buf[8];
#pragma unroll
        for (int u = 0; u < 8; ++u) buf[u] = hp[(size_t)(t0 + u) * En];
#pragma unroll
        for (int u = 0; u < 8; ++u) s = (s + buf[u]) * INV_DECAY;
    }
    g_local[m * NCH + c] = s;
}
__global__ void scan_emit_kernel() {
    const int tid = blockIdx.x * blockDim.x + threadIdx.x;
    const int m = tid >> 12, c = tid & 4095;
    const int b = c >> 9, hd = c & 511;
    float r = 1.f;
#pragma unroll
    for (int q = 0; q < CHUNK; ++q) r *= INV_DECAY;
    float s = 0.f;
    for (int mm = 0; mm < m; ++mm) s = s * r + g_local[mm * NCH + c];
    const float* hp = g_h + (size_t)(b * Tn + m * CHUNK) * En + hd;
    float* Sp = g_S + (size_t)(b * Tn + m * CHUNK) * En + hd;
    for (int t0 = 0; t0 < CHUNK; t0 += 8) {
        float buf[8], sv[8];
#pragma unroll
        for (int u = 0; u < 8; ++u) buf[u] = hp[(size_t)(t0 + u) * En];
#pragma unroll
        for (int u = 0; u < 8; ++u) {
            sv[u] = s;
            s = (s + buf[u]) * INV_DECAY;
        }
#pragma unroll
        for (int u = 0; u < 8; ++u) Sp[(size_t)(t0 + u) * En] = sv[u];
    }
}

// ---------------------------------------------------------------------------
// K3: bilinear via mma.sync bf16 split (unchanged from R4 — passing)
// ---------------------------------------------------------------------------
#define SM_A 0
#define SM_B 18432
#define SM_H 165888
#define SM_Y 186368
#define SM_TOTAL 203264

__global__ __launch_bounds__(256, 1) void bilinear_mma_kernel() {
    extern __shared__ char smem[];
    const uint32_t sb = smem_u32(smem);
    const int tid = threadIdx.x;
    const int wid = tid >> 5, lane = tid & 31;
    const int head = blockIdx.y;
    const int tile = blockIdx.x;
    float* hs = reinterpret_cast<float*>(smem + SM_H);
    float* ys = reinterpret_cast<float*>(smem + SM_Y);

    if (tid < 128) {
        const int r = tid;
        const float* Sp = &g_S[(size_t)(tile * 128 + r) * 512 + head * 32];
        unsigned short sh[32], sl[32];
#pragma unroll
        for (int q = 0; q < 8; ++q) {
            float4 v = *reinterpret_cast<const float4*>(Sp + q * 4);
            float r0, r1, r2, r3;
            sh[q * 4 + 0] = bf_hi(v.x, r0); sh[q * 4 + 1] = bf_hi(v.y, r1);
            sh[q * 4 + 2] = bf_hi(v.z, r2); sh[q * 4 + 3] = bf_hi(v.w, r3);
            sl[q * 4 + 0] = __bfloat16_as_ushort(__float2bfloat16(r0));
            sl[q * 4 + 1] = __bfloat16_as_ushort(__float2bfloat16(r1));
            sl[q * 4 + 2] = __bfloat16_as_ushort(__float2bfloat16(r2));
            sl[q * 4 + 3] = __bfloat16_as_ushort(__float2bfloat16(r3));
        }
        uint4* arow = reinterpret_cast<uint4*>(smem + SM_A + r * 144);
#pragma unroll
        for (int q = 0; q < 4; ++q) {
            uint4 v;
            v.x = (uint32_t)sh[q * 8 + 0] | ((uint32_t)sh[q * 8 + 1] << 16);
            v.y = (uint32_t)sh[q * 8 + 2] | ((uint32_t)sh[q * 8 + 3] << 16);
            v.z = (uint32_t)sh[q * 8 + 4] | ((uint32_t)sh[q * 8 + 5] << 16);
            v.w = (uint32_t)sh[q * 8 + 6] | ((uint32_t)sh[q * 8 + 7] << 16);
            arow[q] = v;
            uint4 w;
            w.x = (uint32_t)sl[q * 8 + 0] | ((uint32_t)sl[q * 8 + 1] << 16);
            w.y = (uint32_t)sl[q * 8 + 2] | ((uint32_t)sl[q * 8 + 3] << 16);
            w.z = (uint32_t)sl[q * 8 + 4] | ((uint32_t)sl[q * 8 + 5] << 16);
            w.w = (uint32_t)sl[q * 8 + 6] | ((uint32_t)sl[q * 8 + 7] << 16);
            arow[4 + q] = w;
        }
    } else {
        const int r = tid - 128;
        const float4* hp = reinterpret_cast<const float4*>(
            &g_h[(size_t)(tile * 128 + r) * 512 + head * 32]);
        float4* hrow = reinterpret_cast<float4*>(&hs[r * 40]);
#pragma unroll
        for (int q = 0; q < 8; ++q) hrow[q] = hp[q];
    }
    {
        const uint4* gsrc = g_Cpack + (size_t)head * 9216;
#pragma unroll
        for (int t = 0; t < 36; ++t) {
            const int gidx = tid + t * 256;
            cp_async16(sb + SM_B + gidx * 16, gsrc + gidx);
        }
        asm volatile("cp.async.commit_group;" ::: "memory");
        asm volatile("cp.async.wait_group 0;" ::: "memory");
    }
    __syncthreads();

    if (wid < 4) {
        const int g = lane >> 2, tg = lane & 3;
        const int m0a = wid * 32, m0b = wid * 32 + 16;
        uint32_t afr[2][4][4];
#pragma unroll
        for (int m = 0; m < 2; ++m) {
            const int mr = (m ? m0b : m0a);
#pragma unroll
            for (int s = 0; s < 4; ++s) {
                const char* base = smem + SM_A;
                afr[m][s][0] = *reinterpret_cast<const uint32_t*>(base + (mr + g) * 144 + (s * 16 + tg * 2) * 2);
                afr[m][s][1] = *reinterpret_cast<const uint32_t*>(base + (mr + g + 8) * 144 + (s * 16 + tg * 2) * 2);
                afr[m][s][2] = *reinterpret_cast<const uint32_t*>(base + (mr + g) * 144 + (s * 16 + 8 + tg * 2) * 2);
                afr[m][s][3] = *reinterpret_cast<const uint32_t*>(base + (mr + g + 8) * 144 + (s * 16 + 8 + tg * 2) * 2);
            }
        }
        float hreg[2][4][4];
#pragma unroll
        for (int m = 0; m < 2; ++m) {
            const int mr = (m ? m0b : m0a);
#pragma unroll
            for (int it = 0; it < 4; ++it) {
                const int i0 = it * 8 + tg * 2;
                hreg[m][it][0] = hs[(mr + g) * 40 + i0];
                hreg[m][it][1] = hs[(mr + g) * 40 + i0 + 1];
                hreg[m][it][2] = hs[(mr + g + 8) * 40 + i0];
                hreg[m][it][3] = hs[(mr + g + 8) * 40 + i0 + 1];
            }
        }
        const uint32_t bbase = sb + SM_B + (lane & 7) * 144 + ((lane >> 3) & 1) * 16;

        for (int k = 0; k < 32; ++k) {
            float yA0 = 0.f, yB0 = 0.f, yA1 = 0.f, yB1 = 0.f;
#pragma unroll
            for (int it = 0; it < 4; ++it) {
                const uint32_t boff = bbase + (uint32_t)(k * 32 + it * 8) * 144;
                uint32_t bh0a, bh0b, bh1a, bh1b, bl0a, bl0b, bl1a, bl1b;
                ldsm_x2(bh0a, bh0b, boff);
                ldsm_x2(bh1a, bh1b, boff + 32);
                ldsm_x2(bl0a, bl0b, boff + 64);
                ldsm_x2(bl1a, bl1b, boff + 96);
#pragma unroll
                for (int m = 0; m < 2; ++m) {
                    float d[4] = {0.f, 0.f, 0.f, 0.f};
                    mma16816(d, afr[m][0], bh0a, bh0b);
                    mma16816(d, afr[m][1], bh1a, bh1b);
                    mma16816(d, afr[m][2], bh0a, bh0b);
                    mma16816(d, afr[m][3], bh1a, bh1b);
                    mma16816(d, afr[m][0], bl0a, bl0b);
                    mma16816(d, afr[m][1], bl1a, bl1b);
                    if (m == 0) {
                        yA0 = fmaf(d[0], hreg[0][it][0], fmaf(d[1], hreg[0][it][1], yA0));
                        yB0 = fmaf(d[2], hreg[0][it][2], fmaf(d[3], hreg[0][it][3], yB0));
                    } else {
                        yA1 = fmaf(d[0], hreg[1][it][0], fmaf(d[1], hreg[1][it][1], yA1));
                        yB1 = fmaf(d[2], hreg[1][it][2], fmaf(d[3], hreg[1][it][3], yB1));
                    }
                }
            }
#pragma unroll
            for (int o = 1; o <= 2; o <<= 1) {
                yA0 += __shfl_xor_sync(0xffffffffu, yA0, o);
                yB0 += __shfl_xor_sync(0xffffffffu, yB0, o);
                yA1 += __shfl_xor_sync(0xffffffffu, yA1, o);
                yB1 += __shfl_xor_sync(0xffffffffu, yB1, o);
            }
            if (tg == (k & 3)) {
                ys[(m0a + g) * 33 + k] = yA0;
                ys[(m0a + g + 8) * 33 + k] = yB0;
                ys[(m0b + g) * 33 + k] = yA1;
                ys[(m0b + g + 8) * 33 + k] = yB1;
            }
        }
    }
    __syncthreads();

#pragma unroll
    for (int p = 0; p < 4; ++p) {
        const int idx = tid + p * 256;
        const int r = idx >> 3, c = (idx & 7) * 4;
        float4 v;
        v.x = ys[r * 33 + c + 0] + hs[r * 40 + c + 0];
        v.y = ys[r * 33 + c + 1] + hs[r * 40 + c + 1];
        v.z = ys[r * 33 + c + 2] + hs[r * 40 + c + 2];
        v.w = ys[r * 33 + c + 3] + hs[r * 40 + c + 3];
        *reinterpret_cast<float4*>(
            &g_y[(size_t)(tile * 128 + r) * 512 + head * 32 + c]) = v;
    }
}

// ---------------------------------------------------------------------------
// K4: LayerNorm
// ---------------------------------------------------------------------------
__global__ __launch_bounds__(256) void ln_kernel(const float* __restrict__ gamma,
                                                 const float* __restrict__ beta,
                                                 float* __restrict__ out) {
    const int w = threadIdx.x >> 5, lane = threadIdx.x & 31;
    const int token = blockIdx.x * 8 + w;
    const float* yp = g_y + (size_t)token * En;
    float vals[16], sum = 0.f, sq = 0.f;
#pragma unroll
    for (int c2 = 0; c2 < 16; ++c2) {
        const float v = yp[c2 * 32 + lane];
        vals[c2] = v; sum += v; sq = fmaf(v, v, sq);
    }
#pragma unroll
    for (int o = 16; o; o >>= 1) {
        sum += __shfl_xor_sync(0xffffffffu, sum, o);
        sq += __shfl_xor_sync(0xffffffffu, sq, o);
    }
    const float mu = sum * (1.f / 512.f);
    const float var = sq * (1.f / 512.f) - mu * mu;
    const float inv = rsqrtf(var + LN_EPS);
    float* op = out + (size_t)token * En;
#pragma unroll
    for (int c2 = 0; c2 < 16; ++c2) {
        const int e = c2 * 32 + lane;
        op[e] = (vals[c2] - mu) * inv * gamma[e] + beta[e];
    }
}

// ---------------------------------------------------------------------------
extern "C" void kernel_launch(void* const* d_in, const int* in_sizes, int n_in,
                              void* d_out, int out_size) {
    const float* x = (const float*)d_in[0];
    const float* W = (const float*)d_in[1];
    const float* bias = (const float*)d_in[2];
    const float* cmap = (const float*)d_in[3];
    const float* gamma = (const float*)d_in[4];
    const float* beta = (const float*)d_in[5];
    float* out = (float*)d_out;

    static int smem_set = 0;
    if (!smem_set) {
        cudaFuncSetAttribute(bilinear_mma_kernel,
                             cudaFuncAttributeMaxDynamicSharedMemorySize, SM_TOTAL);
        cudaFuncSetAttribute(gemm_mma_kernel,
                             cudaFuncAttributeMaxDynamicSharedMemorySize, G_TOTAL);
        smem_set = 1;
    }

    cpack_kernel<<<64, 256>>>(cmap);
    wpack_kernel<<<128, 256>>>(W);
    gemm_mma_kernel<<<dim3(4, 128), 256, G_TOTAL>>>(x, bias);
    scan_local_kernel<<<NCHUNK * NCH / 256, 256>>>();
    scan_emit_kernel<<<NCHUNK * NCH / 256, 256>>>();
    bilinear_mma_kernel<<<dim3(128, Hn), 256, SM_TOTAL>>>();
    ln_kernel<<<BT / 8, 256>>>(gamma, beta, out);
}

// round 7
// speedup vs baseline: 2.6289x; 1.1004x over previous
#include <cuda_runtime.h>
#include <cuda_bf16.h>
#include <cstdint>

// ConceptLayer: h = xW+b ; S = decayed scan ; y = bilinear(h,S;C)+h ; LayerNorm
// B=8 T=2048 E=512 H=16 D=32.  sm_100-safe: mma.sync (HMMA), cp.async, ldmatrix.
#define Bn 8
#define Tn 2048
#define En 512
#define Hn 16
#define BT (Bn * Tn)
#define LN_EPS 1e-3f
#define INV_DECAY (1.0f / 1.2f)
#define CHUNK 128
#define NCHUNK (Tn / CHUNK)
#define NCH (Bn * En)
#define WPITCH 520

__device__ float g_h[BT * En];
__device__ float g_S[BT * En];
__device__ float g_y[BT * En];
__device__ float g_local[NCHUNK * NCH];
// C packed split-bf16: [head][n=k*32+i][72 bf16] = [Ch | Cl | pad]
__device__ uint4 g_Cpack[Hn * 1024 * 9];
// W packed transposed split-bf16: [n][k] pitch 520
__device__ __nv_bfloat16 g_Wh[512 * WPITCH];
__device__ __nv_bfloat16 g_Wl[512 * WPITCH];

__device__ __forceinline__ unsigned short bf_hi(float v, float& rem) {
    __nv_bfloat16 h = __float2bfloat16(v);
    rem = v - __bfloat162float(h);
    return __bfloat16_as_ushort(h);
}
__device__ __forceinline__ uint32_t smem_u32(const void* p) {
    uint32_t a;
    asm("{ .reg .u64 t; cvta.to.shared.u64 t, %1; cvt.u32.u64 %0, t; }" : "=r"(a) : "l"(p));
    return a;
}
__device__ __forceinline__ void mma16816(float* d, const uint32_t* a, uint32_t b0, uint32_t b1) {
    asm volatile(
        "mma.sync.aligned.m16n8k16.row.col.f32.bf16.bf16.f32 "
        "{%0,%1,%2,%3}, {%4,%5,%6,%7}, {%8,%9}, {%0,%1,%2,%3};"
        : "+f"(d[0]), "+f"(d[1]), "+f"(d[2]), "+f"(d[3])
        : "r"(a[0]), "r"(a[1]), "r"(a[2]), "r"(a[3]), "r"(b0), "r"(b1));
}
__device__ __forceinline__ void ldsm_x2(uint32_t& r0, uint32_t& r1, uint32_t addr) {
    asm volatile("ldmatrix.sync.aligned.m8n8.x2.shared.b16 {%0,%1}, [%2];"
                 : "=r"(r0), "=r"(r1) : "r"(addr));
}
__device__ __forceinline__ void cp_async16(uint32_t dst, const void* src) {
    asm volatile("cp.async.cg.shared.global [%0], [%1], 16;" :: "r"(dst), "l"(src) : "memory");
}

// ---------------------------------------------------------------------------
// K0a: pack C -> split bf16 [head][n][72]
// ---------------------------------------------------------------------------
__global__ void cpack_kernel(const float* __restrict__ C) {
    const int idx = blockIdx.x * 256 + threadIdx.x;
    const float* src = C + (size_t)idx * 32;
    unsigned short hi[32], lo[32];
#pragma unroll
    for (int j = 0; j < 32; ++j) {
        float r;
        hi[j] = bf_hi(src[j], r);
        lo[j] = __bfloat16_as_ushort(__float2bfloat16(r));
    }
    uint4* dst = g_Cpack + (size_t)idx * 9;
#pragma unroll
    for (int q = 0; q < 4; ++q) {
        uint4 v;
        v.x = (uint32_t)hi[q * 8 + 0] | ((uint32_t)hi[q * 8 + 1] << 16);
        v.y = (uint32_t)hi[q * 8 + 2] | ((uint32_t)hi[q * 8 + 3] << 16);
        v.z = (uint32_t)hi[q * 8 + 4] | ((uint32_t)hi[q * 8 + 5] << 16);
        v.w = (uint32_t)hi[q * 8 + 6] | ((uint32_t)hi[q * 8 + 7] << 16);
        dst[q] = v;
        uint4 w;
        w.x = (uint32_t)lo[q * 8 + 0] | ((uint32_t)lo[q * 8 + 1] << 16);
        w.y = (uint32_t)lo[q * 8 + 2] | ((uint32_t)lo[q * 8 + 3] << 16);
        w.z = (uint32_t)lo[q * 8 + 4] | ((uint32_t)lo[q * 8 + 5] << 16);
        w.w = (uint32_t)lo[q * 8 + 6] | ((uint32_t)lo[q * 8 + 7] << 16);
        dst[4 + q] = w;
    }
}

// ---------------------------------------------------------------------------
// K0b: pack W [k][n] f32 -> g_Wh/g_Wl [n][k] bf16, pitch WPITCH
// ---------------------------------------------------------------------------
__global__ void wpack_kernel(const float* __restrict__ W) {
    const int n = (blockIdx.x & 1) * 256 + threadIdx.x;
    const int k0 = (blockIdx.x >> 1) * 8;
    unsigned short hi[8], lo[8];
#pragma unroll
    for (int u = 0; u < 8; ++u) {
        float r;
        hi[u] = bf_hi(W[(size_t)(k0 + u) * 512 + n], r);
        lo[u] = __bfloat16_as_ushort(__float2bfloat16(r));
    }
    uint4 vh, vl;
    vh.x = (uint32_t)hi[0] | ((uint32_t)hi[1] << 16);
    vh.y = (uint32_t)hi[2] | ((uint32_t)hi[3] << 16);
    vh.z = (uint32_t)hi[4] | ((uint32_t)hi[5] << 16);
    vh.w = (uint32_t)hi[6] | ((uint32_t)hi[7] << 16);
    vl.x = (uint32_t)lo[0] | ((uint32_t)lo[1] << 16);
    vl.y = (uint32_t)lo[2] | ((uint32_t)lo[3] << 16);
    vl.z = (uint32_t)lo[4] | ((uint32_t)lo[5] << 16);
    vl.w = (uint32_t)lo[6] | ((uint32_t)lo[7] << 16);
    *reinterpret_cast<uint4*>(&g_Wh[(size_t)n * WPITCH + k0]) = vh;
    *reinterpret_cast<uint4*>(&g_Wl[(size_t)n * WPITCH + k0]) = vl;
}

// ---------------------------------------------------------------------------
// K1: h = x @ W + b via mma.sync bf16 split (unchanged; passing)
// ---------------------------------------------------------------------------
#define G_AH 0
#define G_AL 18432
#define G_BH 36864
#define G_BL 55296
#define G_TOTAL 73728

__global__ __launch_bounds__(256, 2) void gemm_mma_kernel(
    const float* __restrict__ x, const float* __restrict__ bias) {
    extern __shared__ char smem[];
    const uint32_t sb = smem_u32(smem);
    const int tid = threadIdx.x;
    const int wid = tid >> 5, lane = tid & 31;
    const int g = lane >> 2, tg = lane & 3;
    const int mw = wid & 3, nw = wid >> 2;
    const int gm0 = blockIdx.y * 128;
    const int gn0 = blockIdx.x * 128;

    float acc[2][8][4];
#pragma unroll
    for (int mt = 0; mt < 2; ++mt)
#pragma unroll
        for (int nt = 0; nt < 8; ++nt)
#pragma unroll
            for (int e = 0; e < 4; ++e) acc[mt][nt][e] = 0.f;

    const int xm = tid >> 1, xh4 = (tid & 1) * 32;
    const uint32_t a_h_dst = sb + G_AH + xm * 144 + xh4 * 2;
    const uint32_t a_l_dst = sb + G_AL + xm * 144 + xh4 * 2;
    const int brow = tid >> 3, bseg = (tid & 7) * 8;

    for (int kc = 0; kc < 8; ++kc) {
#pragma unroll
        for (int it = 0; it < 4; ++it) {
            const int row = brow + it * 32;
            cp_async16(sb + G_BH + row * 144 + bseg * 2,
                       &g_Wh[(size_t)(gn0 + row) * WPITCH + kc * 64 + bseg]);
            cp_async16(sb + G_BL + row * 144 + bseg * 2,
                       &g_Wl[(size_t)(gn0 + row) * WPITCH + kc * 64 + bseg]);
        }
        asm volatile("cp.async.commit_group;" ::: "memory");
        {
            const float4* xs = reinterpret_cast<const float4*>(
                x + (size_t)(gm0 + xm) * 512 + kc * 64 + xh4);
            unsigned short sh[32], sl[32];
#pragma unroll
            for (int q = 0; q < 8; ++q) {
                float4 v = xs[q];
                float r0, r1, r2, r3;
                sh[q * 4 + 0] = bf_hi(v.x, r0); sh[q * 4 + 1] = bf_hi(v.y, r1);
                sh[q * 4 + 2] = bf_hi(v.z, r2); sh[q * 4 + 3] = bf_hi(v.w, r3);
                sl[q * 4 + 0] = __bfloat16_as_ushort(__float2bfloat16(r0));
                sl[q * 4 + 1] = __bfloat16_as_ushort(__float2bfloat16(r1));
                sl[q * 4 + 2] = __bfloat16_as_ushort(__float2bfloat16(r2));
                sl[q * 4 + 3] = __bfloat16_as_ushort(__float2bfloat16(r3));
            }
#pragma unroll
            for (int q = 0; q < 4; ++q) {
                uint4 v;
                v.x = (uint32_t)sh[q * 8 + 0] | ((uint32_t)sh[q * 8 + 1] << 16);
                v.y = (uint32_t)sh[q * 8 + 2] | ((uint32_t)sh[q * 8 + 3] << 16);
                v.z = (uint32_t)sh[q * 8 + 4] | ((uint32_t)sh[q * 8 + 5] << 16);
                v.w = (uint32_t)sh[q * 8 + 6] | ((uint32_t)sh[q * 8 + 7] << 16);
                *reinterpret_cast<uint4*>(smem + (a_h_dst - sb) + q * 16) = v;
                uint4 w;
                w.x = (uint32_t)sl[q * 8 + 0] | ((uint32_t)sl[q * 8 + 1] << 16);
                w.y = (uint32_t)sl[q * 8 + 2] | ((uint32_t)sl[q * 8 + 3] << 16);
                w.z = (uint32_t)sl[q * 8 + 4] | ((uint32_t)sl[q * 8 + 5] << 16);
                w.w = (uint32_t)sl[q * 8 + 6] | ((uint32_t)sl[q * 8 + 7] << 16);
                *reinterpret_cast<uint4*>(smem + (a_l_dst - sb) + q * 16) = w;
            }
        }
        asm volatile("cp.async.wait_group 0;" ::: "memory");
        __syncthreads();

        const uint32_t bb = sb + (lane & 7) * 144 + ((lane >> 3) & 1) * 16 +
                            (nw * 64) * 144;
#pragma unroll
        for (int s = 0; s < 4; ++s) {
            uint32_t ah[2][4], al[2][4];
#pragma unroll
            for (int mt = 0; mt < 2; ++mt) {
                const int mr = mw * 32 + mt * 16;
                const uint32_t ra = (mr + g) * 144 + (s * 16 + tg * 2) * 2;
                const uint32_t rb = (mr + g + 8) * 144 + (s * 16 + tg * 2) * 2;
                ah[mt][0] = *reinterpret_cast<const uint32_t*>(smem + G_AH + ra);
                ah[mt][1] = *reinterpret_cast<const uint32_t*>(smem + G_AH + rb);
                ah[mt][2] = *reinterpret_cast<const uint32_t*>(smem + G_AH + ra + 16);
                ah[mt][3] = *reinterpret_cast<const uint32_t*>(smem + G_AH + rb + 16);
                al[mt][0] = *reinterpret_cast<const uint32_t*>(smem + G_AL + ra);
                al[mt][1] = *reinterpret_cast<const uint32_t*>(smem + G_AL + rb);
                al[mt][2] = *reinterpret_cast<const uint32_t*>(smem + G_AL + ra + 16);
                al[mt][3] = *reinterpret_cast<const uint32_t*>(smem + G_AL + rb + 16);
            }
#pragma unroll
            for (int nt = 0; nt < 8; ++nt) {
                uint32_t bh0, bh1, bl0, bl1;
                const uint32_t bo = bb + nt * 8 * 144 + s * 32;
                ldsm_x2(bh0, bh1, bo + G_BH);
                ldsm_x2(bl0, bl1, bo + G_BL);
#pragma unroll
                for (int mt = 0; mt < 2; ++mt) {
                    mma16816(acc[mt][nt], ah[mt], bh0, bh1);
                    mma16816(acc[mt][nt], al[mt], bh0, bh1);
                    mma16816(acc[mt][nt], ah[mt], bl0, bl1);
                }
            }
        }
        __syncthreads();
    }
#pragma unroll
    for (int nt = 0; nt < 8; ++nt) {
        const int col = gn0 + nw * 64 + nt * 8 + tg * 2;
        const float b0 = __ldg(&bias[col]), b1 = __ldg(&bias[col + 1]);
#pragma unroll
        for (int mt = 0; mt < 2; ++mt) {
            const int row = gm0 + mw * 32 + mt * 16 + g;
            float2 v0 = {acc[mt][nt][0] + b0, acc[mt][nt][1] + b1};
            float2 v1 = {acc[mt][nt][2] + b0, acc[mt][nt][3] + b1};
            *reinterpret_cast<float2*>(&g_h[(size_t)row * 512 + col]) = v0;
            *reinterpret_cast<float2*>(&g_h[(size_t)(row + 8) * 512 + col]) = v1;
        }
    }
}

// ---------------------------------------------------------------------------
// K2: decayed scan — batched loads for MLP
// ---------------------------------------------------------------------------
__global__ void scan_local_kernel() {
    const int tid = blockIdx.x * blockDim.x + threadIdx.x;
    const int m = tid >> 12, c = tid & 4095;
    const int b = c >> 9, hd = c & 511;
    const float* hp = g_h + (size_t)(b * Tn + m * CHUNK) * En + hd;
    float s = 0.f;
    for (int t0 = 0; t0 < CHUNK; t0 += 8) {
        float buf[8];
#pragma unroll
        for (int u = 0; u < 8; ++u) buf[u] = hp[(size_t)(t0 + u) * En];
#pragma unroll
        for (int u = 0; u < 8; ++u) s = (s + buf[u]) * INV_DECAY;
    }
    g_local[m * NCH + c] = s;
}
__global__ void scan_emit_kernel() {
    const int tid = blockIdx.x * blockDim.x + threadIdx.x;
    const int m = tid >> 12, c = tid & 4095;
    const int b = c >> 9, hd = c & 511;
    float r = 1.f;
#pragma unroll
    for (int q = 0; q < CHUNK; ++q) r *= INV_DECAY;
    float s = 0.f;
    for (int mm = 0; mm < m; ++mm) s = s * r + g_local[mm * NCH + c];
    const float* hp = g_h + (size_t)(b * Tn + m * CHUNK) * En + hd;
    float* Sp = g_S + (size_t)(b * Tn + m * CHUNK) * En + hd;
    for (int t0 = 0; t0 < CHUNK; t0 += 8) {
        float buf[8], sv[8];
#pragma unroll
        for (int u = 0; u < 8; ++u) buf[u] = hp[(size_t)(t0 + u) * En];
#pragma unroll
        for (int u = 0; u < 8; ++u) {
            sv[u] = s;
            s = (s + buf[u]) * INV_DECAY;
        }
#pragma unroll
        for (int u = 0; u < 8; ++u) Sp[(size_t)(t0 + u) * En] = sv[u];
    }
}

// ---------------------------------------------------------------------------
// K3: bilinear via mma.sync bf16 split.
// Block = (256 tokens, head), 2 phases of 128 tokens reusing resident C.
// 8 compute warps x 1 m-tile (16 rows) per phase. C cp.async issued first.
// ---------------------------------------------------------------------------
#define SM_A 0
#define SM_B 18432
#define SM_H 165888
#define SM_Y 186368
#define SM_TOTAL 203264

__global__ __launch_bounds__(256, 1) void bilinear_mma_kernel() {
    extern __shared__ char smem[];
    const uint32_t sb = smem_u32(smem);
    const int tid = threadIdx.x;
    const int wid = tid >> 5, lane = tid & 31;
    const int head = blockIdx.y;
    const int tile = blockIdx.x;          // 64 tiles of 256 tokens
    float* hs = reinterpret_cast<float*>(smem + SM_H);
    float* ys = reinterpret_cast<float*>(smem + SM_Y);

    // C prefetch FIRST (hidden behind phase-0 A pack)
    {
        const uint4* gsrc = g_Cpack + (size_t)head * 9216;
#pragma unroll
        for (int t = 0; t < 36; ++t) {
            const int gidx = tid + t * 256;
            cp_async16(sb + SM_B + gidx * 16, gsrc + gidx);
        }
        asm volatile("cp.async.commit_group;" ::: "memory");
    }

    const int g = lane >> 2, tg = lane & 3;
    const int m0 = wid * 16;
    const uint32_t bbase = sb + SM_B + (lane & 7) * 144 + ((lane >> 3) & 1) * 16;

    for (int ph = 0; ph < 2; ++ph) {
        const int tok0 = tile * 256 + ph * 128;
        // ---- A pack (tid<128) / h copy (tid>=128)
        if (tid < 128) {
            const int r = tid;
            const float* Sp = &g_S[(size_t)(tok0 + r) * 512 + head * 32];
            unsigned short sh[32], sl[32];
#pragma unroll
            for (int q = 0; q < 8; ++q) {
                float4 v = *reinterpret_cast<const float4*>(Sp + q * 4);
                float r0, r1, r2, r3;
                sh[q * 4 + 0] = bf_hi(v.x, r0); sh[q * 4 + 1] = bf_hi(v.y, r1);
                sh[q * 4 + 2] = bf_hi(v.z, r2); sh[q * 4 + 3] = bf_hi(v.w, r3);
                sl[q * 4 + 0] = __bfloat16_as_ushort(__float2bfloat16(r0));
                sl[q * 4 + 1] = __bfloat16_as_ushort(__float2bfloat16(r1));
                sl[q * 4 + 2] = __bfloat16_as_ushort(__float2bfloat16(r2));
                sl[q * 4 + 3] = __bfloat16_as_ushort(__float2bfloat16(r3));
            }
            uint4* arow = reinterpret_cast<uint4*>(smem + SM_A + r * 144);
#pragma unroll
            for (int q = 0; q < 4; ++q) {
                uint4 v;
                v.x = (uint32_t)sh[q * 8 + 0] | ((uint32_t)sh[q * 8 + 1] << 16);
                v.y = (uint32_t)sh[q * 8 + 2] | ((uint32_t)sh[q * 8 + 3] << 16);
                v.z = (uint32_t)sh[q * 8 + 4] | ((uint32_t)sh[q * 8 + 5] << 16);
                v.w = (uint32_t)sh[q * 8 + 6] | ((uint32_t)sh[q * 8 + 7] << 16);
                arow[q] = v;
                uint4 w;
                w.x = (uint32_t)sl[q * 8 + 0] | ((uint32_t)sl[q * 8 + 1] << 16);
                w.y = (uint32_t)sl[q * 8 + 2] | ((uint32_t)sl[q * 8 + 3] << 16);
                w.z = (uint32_t)sl[q * 8 + 4] | ((uint32_t)sl[q * 8 + 5] << 16);
                w.w = (uint32_t)sl[q * 8 + 6] | ((uint32_t)sl[q * 8 + 7] << 16);
                arow[4 + q] = w;
            }
        } else {
            const int r = tid - 128;
            const float4* hp = reinterpret_cast<const float4*>(
                &g_h[(size_t)(tok0 + r) * 512 + head * 32]);
            float4* hrow = reinterpret_cast<float4*>(&hs[r * 40]);
#pragma unroll
            for (int q = 0; q < 8; ++q) hrow[q] = hp[q];
        }
        if (ph == 0) asm volatile("cp.async.wait_group 0;" ::: "memory");
        __syncthreads();

        // ---- compute: 8 warps, 16 rows each
        {
            uint32_t afr[4][4];
#pragma unroll
            for (int s = 0; s < 4; ++s) {
                const char* base = smem + SM_A;
                const uint32_t ra = (m0 + g) * 144 + (s * 16 + tg * 2) * 2;
                const uint32_t rb = (m0 + g + 8) * 144 + (s * 16 + tg * 2) * 2;
                afr[s][0] = *reinterpret_cast<const uint32_t*>(base + ra);
                afr[s][1] = *reinterpret_cast<const uint32_t*>(base + rb);
                afr[s][2] = *reinterpret_cast<const uint32_t*>(base + ra + 16);
                afr[s][3] = *reinterpret_cast<const uint32_t*>(base + rb + 16);
            }
            float hreg[4][4];
#pragma unroll
            for (int it = 0; it < 4; ++it) {
                const int i0 = it * 8 + tg * 2;
                hreg[it][0] = hs[(m0 + g) * 40 + i0];
                hreg[it][1] = hs[(m0 + g) * 40 + i0 + 1];
                hreg[it][2] = hs[(m0 + g + 8) * 40 + i0];
                hreg[it][3] = hs[(m0 + g + 8) * 40 + i0 + 1];
            }

            for (int k = 0; k < 32; ++k) {
                float yA = 0.f, yB = 0.f;
#pragma unroll
                for (int it = 0; it < 4; ++it) {
                    const uint32_t boff = bbase + (uint32_t)(k * 32 + it * 8) * 144;
                    uint32_t bh0, bh1, bh2, bh3, bl0, bl1, bl2, bl3;
                    ldsm_x2(bh0, bh1, boff);
                    ldsm_x2(bh2, bh3, boff + 32);
                    ldsm_x2(bl0, bl1, boff + 64);
                    ldsm_x2(bl2, bl3, boff + 96);
                    float d[4] = {0.f, 0.f, 0.f, 0.f};
                    mma16816(d, afr[0], bh0, bh1);   // Sh.Ch lo-k
                    mma16816(d, afr[1], bh2, bh3);   // Sh.Ch hi-k
                    mma16816(d, afr[2], bh0, bh1);   // Sl.Ch lo-k
                    mma16816(d, afr[3], bh2, bh3);   // Sl.Ch hi-k
                    mma16816(d, afr[0], bl0, bl1);   // Sh.Cl lo-k
                    mma16816(d, afr[1], bl2, bl3);   // Sh.Cl hi-k
                    yA = fmaf(d[0], hreg[it][0], fmaf(d[1], hreg[it][1], yA));
                    yB = fmaf(d[2], hreg[it][2], fmaf(d[3], hreg[it][3], yB));
                }
#pragma unroll
                for (int o = 1; o <= 2; o <<= 1) {
                    yA += __shfl_xor_sync(0xffffffffu, yA, o);
                    yB += __shfl_xor_sync(0xffffffffu, yB, o);
                }
                if (tg == (k & 3)) {
                    ys[(m0 + g) * 33 + k] = yA;
                    ys[(m0 + g + 8) * 33 + k] = yB;
                }
            }
        }
        __syncthreads();

        // ---- residual + coalesced store
#pragma unroll
        for (int p = 0; p < 4; ++p) {
            const int idx = tid + p * 256;
            const int r = idx >> 3, c = (idx & 7) * 4;
            float4 v;
            v.x = ys[r * 33 + c + 0] + hs[r * 40 + c + 0];
            v.y = ys[r * 33 + c + 1] + hs[r * 40 + c + 1];
            v.z = ys[r * 33 + c + 2] + hs[r * 40 + c + 2];
            v.w = ys[r * 33 + c + 3] + hs[r * 40 + c + 3];
            *reinterpret_cast<float4*>(
                &g_y[(size_t)(tok0 + r) * 512 + head * 32 + c]) = v;
        }
        if (ph == 0) __syncthreads();
    }
}

// ---------------------------------------------------------------------------
// K4: LayerNorm
// ---------------------------------------------------------------------------
__global__ __launch_bounds__(256) void ln_kernel(const float* __restrict__ gamma,
                                                 const float* __restrict__ beta,
                                                 float* __restrict__ out) {
    const int w = threadIdx.x >> 5, lane = threadIdx.x & 31;
    const int token = blockIdx.x * 8 + w;
    const float* yp = g_y + (size_t)token * En;
    float vals[16], sum = 0.f, sq = 0.f;
#pragma unroll
    for (int c2 = 0; c2 < 16; ++c2) {
        const float v = yp[c2 * 32 + lane];
        vals[c2] = v; sum += v; sq = fmaf(v, v, sq);
    }
#pragma unroll
    for (int o = 16; o; o >>= 1) {
        sum += __shfl_xor_sync(0xffffffffu, sum, o);
        sq += __shfl_xor_sync(0xffffffffu, sq, o);
    }
    const float mu = sum * (1.f / 512.f);
    const float var = sq * (1.f / 512.f) - mu * mu;
    const float inv = rsqrtf(var + LN_EPS);
    float* op = out + (size_t)token * En;
#pragma unroll
    for (int c2 = 0; c2 < 16; ++c2) {
        const int e = c2 * 32 + lane;
        op[e] = (vals[c2] - mu) * inv * gamma[e] + beta[e];
    }
}

// ---------------------------------------------------------------------------
extern "C" void kernel_launch(void* const* d_in, const int* in_sizes, int n_in,
                              void* d_out, int out_size) {
    const float* x = (const float*)d_in[0];
    const float* W = (const float*)d_in[1];
    const float* bias = (const float*)d_in[2];
    const float* cmap = (const float*)d_in[3];
    const float* gamma = (const float*)d_in[4];
    const float* beta = (const float*)d_in[5];
    float* out = (float*)d_out;

    static int smem_set = 0;
    if (!smem_set) {
        cudaFuncSetAttribute(bilinear_mma_kernel,
                             cudaFuncAttributeMaxDynamicSharedMemorySize, SM_TOTAL);
        cudaFuncSetAttribute(gemm_mma_kernel,
                             cudaFuncAttributeMaxDynamicSharedMemorySize, G_TOTAL);
        smem_set = 1;
    }

    cpack_kernel<<<64, 256>>>(cmap);
    wpack_kernel<<<128, 256>>>(W);
    gemm_mma_kernel<<<dim3(4, 128), 256, G_TOTAL>>>(x, bias);
    scan_local_kernel<<<NCHUNK * NCH / 256, 256>>>();
    scan_emit_kernel<<<NCHUNK * NCH / 256, 256>>>();
    bilinear_mma_kernel<<<dim3(64, Hn), 256, SM_TOTAL>>>();
    ln_kernel<<<BT / 8, 256>>>(gamma, beta, out);
}

// round 8
// speedup vs baseline: 2.7286x; 1.0379x over previous
#include <cuda_runtime.h>
#include <cuda_bf16.h>
#include <cstdint>

// ConceptLayer: h = xW+b ; S = decayed scan ; y = bilinear(h,S;C)+h ; LayerNorm
// B=8 T=2048 E=512 H=16 D=32.  sm_100-safe: mma.sync (HMMA), cp.async, ldmatrix.
#define Bn 8
#define Tn 2048
#define En 512
#define Hn 16
#define BT (Bn * Tn)
#define LN_EPS 1e-3f
#define INV_DECAY (1.0f / 1.2f)
#define CHUNK 128
#define NCHUNK (Tn / CHUNK)
#define NCH (Bn * En)
#define WPITCH 520

__device__ float g_h[BT * En];
__device__ float g_S[BT * En];
__device__ float g_y[BT * En];
__device__ float g_local[NCHUNK * NCH];
// C packed split-bf16: [head][n=k*32+i][72 bf16] = [Ch | Cl | pad]
__device__ uint4 g_Cpack[Hn * 1024 * 9];
// W packed transposed split-bf16: [n][k] pitch 520
__device__ __nv_bfloat16 g_Wh[512 * WPITCH];
__device__ __nv_bfloat16 g_Wl[512 * WPITCH];

__device__ __forceinline__ unsigned short bf_hi(float v, float& rem) {
    __nv_bfloat16 h = __float2bfloat16(v);
    rem = v - __bfloat162float(h);
    return __bfloat16_as_ushort(h);
}
__device__ __forceinline__ uint32_t smem_u32(const void* p) {
    uint32_t a;
    asm("{ .reg .u64 t; cvta.to.shared.u64 t, %1; cvt.u32.u64 %0, t; }" : "=r"(a) : "l"(p));
    return a;
}
__device__ __forceinline__ void mma16816(float* d, const uint32_t* a, uint32_t b0, uint32_t b1) {
    asm volatile(
        "mma.sync.aligned.m16n8k16.row.col.f32.bf16.bf16.f32 "
        "{%0,%1,%2,%3}, {%4,%5,%6,%7}, {%8,%9}, {%0,%1,%2,%3};"
        : "+f"(d[0]), "+f"(d[1]), "+f"(d[2]), "+f"(d[3])
        : "r"(a[0]), "r"(a[1]), "r"(a[2]), "r"(a[3]), "r"(b0), "r"(b1));
}
__device__ __forceinline__ void ldsm_x2(uint32_t& r0, uint32_t& r1, uint32_t addr) {
    asm volatile("ldmatrix.sync.aligned.m8n8.x2.shared.b16 {%0,%1}, [%2];"
                 : "=r"(r0), "=r"(r1) : "r"(addr));
}
__device__ __forceinline__ void ldsm_x4(uint32_t* r, uint32_t addr) {
    asm volatile("ldmatrix.sync.aligned.m8n8.x4.shared.b16 {%0,%1,%2,%3}, [%4];"
                 : "=r"(r[0]), "=r"(r[1]), "=r"(r[2]), "=r"(r[3]) : "r"(addr));
}
__device__ __forceinline__ void cp_async16(uint32_t dst, const void* src) {
    asm volatile("cp.async.cg.shared.global [%0], [%1], 16;" :: "r"(dst), "l"(src) : "memory");
}

// ---------------------------------------------------------------------------
// K0a: pack C -> split bf16 [head][n][72]
// ---------------------------------------------------------------------------
__global__ void cpack_kernel(const float* __restrict__ C) {
    const int idx = blockIdx.x * 256 + threadIdx.x;
    const float* src = C + (size_t)idx * 32;
    unsigned short hi[32], lo[32];
#pragma unroll
    for (int j = 0; j < 32; ++j) {
        float r;
        hi[j] = bf_hi(src[j], r);
        lo[j] = __bfloat16_as_ushort(__float2bfloat16(r));
    }
    uint4* dst = g_Cpack + (size_t)idx * 9;
#pragma unroll
    for (int q = 0; q < 4; ++q) {
        uint4 v;
        v.x = (uint32_t)hi[q * 8 + 0] | ((uint32_t)hi[q * 8 + 1] << 16);
        v.y = (uint32_t)hi[q * 8 + 2] | ((uint32_t)hi[q * 8 + 3] << 16);
        v.z = (uint32_t)hi[q * 8 + 4] | ((uint32_t)hi[q * 8 + 5] << 16);
        v.w = (uint32_t)hi[q * 8 + 6] | ((uint32_t)hi[q * 8 + 7] << 16);
        dst[q] = v;
        uint4 w;
        w.x = (uint32_t)lo[q * 8 + 0] | ((uint32_t)lo[q * 8 + 1] << 16);
        w.y = (uint32_t)lo[q * 8 + 2] | ((uint32_t)lo[q * 8 + 3] << 16);
        w.z = (uint32_t)lo[q * 8 + 4] | ((uint32_t)lo[q * 8 + 5] << 16);
        w.w = (uint32_t)lo[q * 8 + 6] | ((uint32_t)lo[q * 8 + 7] << 16);
        dst[4 + q] = w;
    }
}

// ---------------------------------------------------------------------------
// K0b: pack W [k][n] f32 -> g_Wh/g_Wl [n][k] bf16, pitch WPITCH
// ---------------------------------------------------------------------------
__global__ void wpack_kernel(const float* __restrict__ W) {
    const int n = (blockIdx.x & 1) * 256 + threadIdx.x;
    const int k0 = (blockIdx.x >> 1) * 8;
    unsigned short hi[8], lo[8];
#pragma unroll
    for (int u = 0; u < 8; ++u) {
        float r;
        hi[u] = bf_hi(W[(size_t)(k0 + u) * 512 + n], r);
        lo[u] = __bfloat16_as_ushort(__float2bfloat16(r));
    }
    uint4 vh, vl;
    vh.x = (uint32_t)hi[0] | ((uint32_t)hi[1] << 16);
    vh.y = (uint32_t)hi[2] | ((uint32_t)hi[3] << 16);
    vh.z = (uint32_t)hi[4] | ((uint32_t)hi[5] << 16);
    vh.w = (uint32_t)hi[6] | ((uint32_t)hi[7] << 16);
    vl.x = (uint32_t)lo[0] | ((uint32_t)lo[1] << 16);
    vl.y = (uint32_t)lo[2] | ((uint32_t)lo[3] << 16);
    vl.z = (uint32_t)lo[4] | ((uint32_t)lo[5] << 16);
    vl.w = (uint32_t)lo[6] | ((uint32_t)lo[7] << 16);
    *reinterpret_cast<uint4*>(&g_Wh[(size_t)n * WPITCH + k0]) = vh;
    *reinterpret_cast<uint4*>(&g_Wl[(size_t)n * WPITCH + k0]) = vl;
}

// ---------------------------------------------------------------------------
// K1: h = x @ W + b via mma.sync bf16 split (unchanged; passing)
// ---------------------------------------------------------------------------
#define G_AH 0
#define G_AL 18432
#define G_BH 36864
#define G_BL 55296
#define G_TOTAL 73728

__global__ __launch_bounds__(256, 2) void gemm_mma_kernel(
    const float* __restrict__ x, const float* __restrict__ bias) {
    extern __shared__ char smem[];
    const uint32_t sb = smem_u32(smem);
    const int tid = threadIdx.x;
    const int wid = tid >> 5, lane = tid & 31;
    const int g = lane >> 2, tg = lane & 3;
    const int mw = wid & 3, nw = wid >> 2;
    const int gm0 = blockIdx.y * 128;
    const int gn0 = blockIdx.x * 128;

    float acc[2][8][4];
#pragma unroll
    for (int mt = 0; mt < 2; ++mt)
#pragma unroll
        for (int nt = 0; nt < 8; ++nt)
#pragma unroll
            for (int e = 0; e < 4; ++e) acc[mt][nt][e] = 0.f;

    const int xm = tid >> 1, xh4 = (tid & 1) * 32;
    const uint32_t a_h_dst = sb + G_AH + xm * 144 + xh4 * 2;
    const uint32_t a_l_dst = sb + G_AL + xm * 144 + xh4 * 2;
    const int brow = tid >> 3, bseg = (tid & 7) * 8;

    for (int kc = 0; kc < 8; ++kc) {
#pragma unroll
        for (int it = 0; it < 4; ++it) {
            const int row = brow + it * 32;
            cp_async16(sb + G_BH + row * 144 + bseg * 2,
                       &g_Wh[(size_t)(gn0 + row) * WPITCH + kc * 64 + bseg]);
            cp_async16(sb + G_BL + row * 144 + bseg * 2,
                       &g_Wl[(size_t)(gn0 + row) * WPITCH + kc * 64 + bseg]);
        }
        asm volatile("cp.async.commit_group;" ::: "memory");
        {
            const float4* xs = reinterpret_cast<const float4*>(
                x + (size_t)(gm0 + xm) * 512 + kc * 64 + xh4);
            unsigned short sh[32], sl[32];
#pragma unroll
            for (int q = 0; q < 8; ++q) {
                float4 v = xs[q];
                float r0, r1, r2, r3;
                sh[q * 4 + 0] = bf_hi(v.x, r0); sh[q * 4 + 1] = bf_hi(v.y, r1);
                sh[q * 4 + 2] = bf_hi(v.z, r2); sh[q * 4 + 3] = bf_hi(v.w, r3);
                sl[q * 4 + 0] = __bfloat16_as_ushort(__float2bfloat16(r0));
                sl[q * 4 + 1] = __bfloat16_as_ushort(__float2bfloat16(r1));
                sl[q * 4 + 2] = __bfloat16_as_ushort(__float2bfloat16(r2));
                sl[q * 4 + 3] = __bfloat16_as_ushort(__float2bfloat16(r3));
            }
#pragma unroll
            for (int q = 0; q < 4; ++q) {
                uint4 v;
                v.x = (uint32_t)sh[q * 8 + 0] | ((uint32_t)sh[q * 8 + 1] << 16);
                v.y = (uint32_t)sh[q * 8 + 2] | ((uint32_t)sh[q * 8 + 3] << 16);
                v.z = (uint32_t)sh[q * 8 + 4] | ((uint32_t)sh[q * 8 + 5] << 16);
                v.w = (uint32_t)sh[q * 8 + 6] | ((uint32_t)sh[q * 8 + 7] << 16);
                *reinterpret_cast<uint4*>(smem + (a_h_dst - sb) + q * 16) = v;
                uint4 w;
                w.x = (uint32_t)sl[q * 8 + 0] | ((uint32_t)sl[q * 8 + 1] << 16);
                w.y = (uint32_t)sl[q * 8 + 2] | ((uint32_t)sl[q * 8 + 3] << 16);
                w.z = (uint32_t)sl[q * 8 + 4] | ((uint32_t)sl[q * 8 + 5] << 16);
                w.w = (uint32_t)sl[q * 8 + 6] | ((uint32_t)sl[q * 8 + 7] << 16);
                *reinterpret_cast<uint4*>(smem + (a_l_dst - sb) + q * 16) = w;
            }
        }
        asm volatile("cp.async.wait_group 0;" ::: "memory");
        __syncthreads();

        const uint32_t bb = sb + (lane & 7) * 144 + ((lane >> 3) & 1) * 16 +
                            (nw * 64) * 144;
#pragma unroll
        for (int s = 0; s < 4; ++s) {
            uint32_t ah[2][4], al[2][4];
#pragma unroll
            for (int mt = 0; mt < 2; ++mt) {
                const int mr = mw * 32 + mt * 16;
                const uint32_t ra = (mr + g) * 144 + (s * 16 + tg * 2) * 2;
                const uint32_t rb = (mr + g + 8) * 144 + (s * 16 + tg * 2) * 2;
                ah[mt][0] = *reinterpret_cast<const uint32_t*>(smem + G_AH + ra);
                ah[mt][1] = *reinterpret_cast<const uint32_t*>(smem + G_AH + rb);
                ah[mt][2] = *reinterpret_cast<const uint32_t*>(smem + G_AH + ra + 16);
                ah[mt][3] = *reinterpret_cast<const uint32_t*>(smem + G_AH + rb + 16);
                al[mt][0] = *reinterpret_cast<const uint32_t*>(smem + G_AL + ra);
                al[mt][1] = *reinterpret_cast<const uint32_t*>(smem + G_AL + rb);
                al[mt][2] = *reinterpret_cast<const uint32_t*>(smem + G_AL + ra + 16);
                al[mt][3] = *reinterpret_cast<const uint32_t*>(smem + G_AL + rb + 16);
            }
#pragma unroll
            for (int nt = 0; nt < 8; ++nt) {
                uint32_t bh0, bh1, bl0, bl1;
                const uint32_t bo = bb + nt * 8 * 144 + s * 32;
                ldsm_x2(bh0, bh1, bo + G_BH);
                ldsm_x2(bl0, bl1, bo + G_BL);
#pragma unroll
                for (int mt = 0; mt < 2; ++mt) {
                    mma16816(acc[mt][nt], ah[mt], bh0, bh1);
                    mma16816(acc[mt][nt], al[mt], bh0, bh1);
                    mma16816(acc[mt][nt], ah[mt], bl0, bl1);
                }
            }
        }
        __syncthreads();
    }
#pragma unroll
    for (int nt = 0; nt < 8; ++nt) {
        const int col = gn0 + nw * 64 + nt * 8 + tg * 2;
        const float b0 = __ldg(&bias[col]), b1 = __ldg(&bias[col + 1]);
#pragma unroll
        for (int mt = 0; mt < 2; ++mt) {
            const int row = gm0 + mw * 32 + mt * 16 + g;
            float2 v0 = {acc[mt][nt][0] + b0, acc[mt][nt][1] + b1};
            float2 v1 = {acc[mt][nt][2] + b0, acc[mt][nt][3] + b1};
            *reinterpret_cast<float2*>(&g_h[(size_t)row * 512 + col]) = v0;
            *reinterpret_cast<float2*>(&g_h[(size_t)(row + 8) * 512 + col]) = v1;
        }
    }
}

// ---------------------------------------------------------------------------
// K2: decayed scan — batched loads for MLP
// ---------------------------------------------------------------------------
__global__ void scan_local_kernel() {
    const int tid = blockIdx.x * blockDim.x + threadIdx.x;
    const int m = tid >> 12, c = tid & 4095;
    const int b = c >> 9, hd = c & 511;
    const float* hp = g_h + (size_t)(b * Tn + m * CHUNK) * En + hd;
    float s = 0.f;
    for (int t0 = 0; t0 < CHUNK; t0 += 8) {
        float buf[8];
#pragma unroll
        for (int u = 0; u < 8; ++u) buf[u] = hp[(size_t)(t0 + u) * En];
#pragma unroll
        for (int u = 0; u < 8; ++u) s = (s + buf[u]) * INV_DECAY;
    }
    g_local[m * NCH + c] = s;
}
__global__ void scan_emit_kernel() {
    const int tid = blockIdx.x * blockDim.x + threadIdx.x;
    const int m = tid >> 12, c = tid & 4095;
    const int b = c >> 9, hd = c & 511;
    float r = 1.f;
#pragma unroll
    for (int q = 0; q < CHUNK; ++q) r *= INV_DECAY;
    float s = 0.f;
    for (int mm = 0; mm < m; ++mm) s = s * r + g_local[mm * NCH + c];
    const float* hp = g_h + (size_t)(b * Tn + m * CHUNK) * En + hd;
    float* Sp = g_S + (size_t)(b * Tn + m * CHUNK) * En + hd;
    for (int t0 = 0; t0 < CHUNK; t0 += 8) {
        float buf[8], sv[8];
#pragma unroll
        for (int u = 0; u < 8; ++u) buf[u] = hp[(size_t)(t0 + u) * En];
#pragma unroll
        for (int u = 0; u < 8; ++u) {
            sv[u] = s;
            s = (s + buf[u]) * INV_DECAY;
        }
#pragma unroll
        for (int u = 0; u < 8; ++u) Sp[(size_t)(t0 + u) * En] = sv[u];
    }
}

// ---------------------------------------------------------------------------
// K3: bilinear via mma.sync bf16 split — single 256-token phase.
// 8 warps x 2 m-tiles (16 rows each) = 256 rows; C frags via ldmatrix.x4,
// each fragment feeds 2 MMA chains. h read straight from g_h (L2).
// ---------------------------------------------------------------------------
#define SM_A 0            // 256*144  = 36864
#define SM_B 36864        // 1024*144 = 147456
#define SM_Y 184320       // 256*33*4 = 33792
#define SM_TOTAL 218112

__global__ __launch_bounds__(256, 1) void bilinear_mma_kernel() {
    extern __shared__ char smem[];
    const uint32_t sb = smem_u32(smem);
    const int tid = threadIdx.x;
    const int wid = tid >> 5, lane = tid & 31;
    const int head = blockIdx.y;
    const int tok0 = blockIdx.x * 256;
    float* ys = reinterpret_cast<float*>(smem + SM_Y);

    // C prefetch FIRST (hidden behind A pack)
    {
        const uint4* gsrc = g_Cpack + (size_t)head * 9216;
#pragma unroll
        for (int t = 0; t < 36; ++t) {
            const int gidx = tid + t * 256;
            cp_async16(sb + SM_B + gidx * 16, gsrc + gidx);
        }
        asm volatile("cp.async.commit_group;" ::: "memory");
    }

    // A pack: each thread packs one of 256 rows
    {
        const int r = tid;
        const float* Sp = &g_S[(size_t)(tok0 + r) * 512 + head * 32];
        unsigned short sh[32], sl[32];
#pragma unroll
        for (int q = 0; q < 8; ++q) {
            float4 v = *reinterpret_cast<const float4*>(Sp + q * 4);
            float r0, r1, r2, r3;
            sh[q * 4 + 0] = bf_hi(v.x, r0); sh[q * 4 + 1] = bf_hi(v.y, r1);
            sh[q * 4 + 2] = bf_hi(v.z, r2); sh[q * 4 + 3] = bf_hi(v.w, r3);
            sl[q * 4 + 0] = __bfloat16_as_ushort(__float2bfloat16(r0));
            sl[q * 4 + 1] = __bfloat16_as_ushort(__float2bfloat16(r1));
            sl[q * 4 + 2] = __bfloat16_as_ushort(__float2bfloat16(r2));
            sl[q * 4 + 3] = __bfloat16_as_ushort(__float2bfloat16(r3));
        }
        uint4* arow = reinterpret_cast<uint4*>(smem + SM_A + r * 144);
#pragma unroll
        for (int q = 0; q < 4; ++q) {
            uint4 v;
            v.x = (uint32_t)sh[q * 8 + 0] | ((uint32_t)sh[q * 8 + 1] << 16);
            v.y = (uint32_t)sh[q * 8 + 2] | ((uint32_t)sh[q * 8 + 3] << 16);
            v.z = (uint32_t)sh[q * 8 + 4] | ((uint32_t)sh[q * 8 + 5] << 16);
            v.w = (uint32_t)sh[q * 8 + 6] | ((uint32_t)sh[q * 8 + 7] << 16);
            arow[q] = v;
            uint4 w;
            w.x = (uint32_t)sl[q * 8 + 0] | ((uint32_t)sl[q * 8 + 1] << 16);
            w.y = (uint32_t)sl[q * 8 + 2] | ((uint32_t)sl[q * 8 + 3] << 16);
            w.z = (uint32_t)sl[q * 8 + 4] | ((uint32_t)sl[q * 8 + 5] << 16);
            w.w = (uint32_t)sl[q * 8 + 6] | ((uint32_t)sl[q * 8 + 7] << 16);
            arow[4 + q] = w;
        }
    }
    asm volatile("cp.async.wait_group 0;" ::: "memory");
    __syncthreads();

    {
        const int g = lane >> 2, tg = lane & 3;
        // A fragments + h registers for 2 m-tiles
        uint32_t afr[2][4][4];
        float hreg[2][4][4];
#pragma unroll
        for (int mt = 0; mt < 2; ++mt) {
            const int mr = (wid * 2 + mt) * 16;
#pragma unroll
            for (int s = 0; s < 4; ++s) {
                const char* base = smem + SM_A;
                const uint32_t ra = (mr + g) * 144 + (s * 16 + tg * 2) * 2;
                const uint32_t rb = (mr + g + 8) * 144 + (s * 16 + tg * 2) * 2;
                afr[mt][s][0] = *reinterpret_cast<const uint32_t*>(base + ra);
                afr[mt][s][1] = *reinterpret_cast<const uint32_t*>(base + rb);
                afr[mt][s][2] = *reinterpret_cast<const uint32_t*>(base + ra + 16);
                afr[mt][s][3] = *reinterpret_cast<const uint32_t*>(base + rb + 16);
            }
#pragma unroll
            for (int it = 0; it < 4; ++it) {
                const int i0 = it * 8 + tg * 2;
                float2 va = *reinterpret_cast<const float2*>(
                    &g_h[(size_t)(tok0 + mr + g) * 512 + head * 32 + i0]);
                float2 vb = *reinterpret_cast<const float2*>(
                    &g_h[(size_t)(tok0 + mr + g + 8) * 512 + head * 32 + i0]);
                hreg[mt][it][0] = va.x; hreg[mt][it][1] = va.y;
                hreg[mt][it][2] = vb.x; hreg[mt][it][3] = vb.y;
            }
        }
        // ldmatrix.x4 lane addressing: lanes 0-7 tile0 (j0-7), 8-15 tile1 (j8-15),
        // 16-23 tile2 (j16-23), 24-31 tile3 (j24-31)
        const uint32_t bb4 = sb + SM_B + (lane & 7) * 144 + ((lane >> 3) & 3) * 16;

        for (int k = 0; k < 32; ++k) {
            float yA0 = 0.f, yB0 = 0.f, yA1 = 0.f, yB1 = 0.f;
#pragma unroll
            for (int it = 0; it < 4; ++it) {
                const uint32_t boff = bb4 + (uint32_t)(k * 32 + it * 8) * 144;
                uint32_t bh[4], bl[4];
                ldsm_x4(bh, boff);        // Ch: (bh0,bh1)=j0-15, (bh2,bh3)=j16-31
                ldsm_x4(bl, boff + 64);   // Cl
#pragma unroll
                for (int mt = 0; mt < 2; ++mt) {
                    float d[4] = {0.f, 0.f, 0.f, 0.f};
                    mma16816(d, afr[mt][0], bh[0], bh[1]);   // Sh.Ch lo-k
                    mma16816(d, afr[mt][1], bh[2], bh[3]);   // Sh.Ch hi-k
                    mma16816(d, afr[mt][2], bh[0], bh[1]);   // Sl.Ch lo-k
                    mma16816(d, afr[mt][3], bh[2], bh[3]);   // Sl.Ch hi-k
                    mma16816(d, afr[mt][0], bl[0], bl[1]);   // Sh.Cl lo-k
                    mma16816(d, afr[mt][1], bl[2], bl[3]);   // Sh.Cl hi-k
                    if (mt == 0) {
                        yA0 = fmaf(d[0], hreg[0][it][0], fmaf(d[1], hreg[0][it][1], yA0));
                        yB0 = fmaf(d[2], hreg[0][it][2], fmaf(d[3], hreg[0][it][3], yB0));
                    } else {
                        yA1 = fmaf(d[0], hreg[1][it][0], fmaf(d[1], hreg[1][it][1], yA1));
                        yB1 = fmaf(d[2], hreg[1][it][2], fmaf(d[3], hreg[1][it][3], yB1));
                    }
                }
            }
#pragma unroll
            for (int o = 1; o <= 2; o <<= 1) {
                yA0 += __shfl_xor_sync(0xffffffffu, yA0, o);
                yB0 += __shfl_xor_sync(0xffffffffu, yB0, o);
                yA1 += __shfl_xor_sync(0xffffffffu, yA1, o);
                yB1 += __shfl_xor_sync(0xffffffffu, yB1, o);
            }
            if (tg == (k & 3)) {
                const int mrA = (wid * 2) * 16, mrB = (wid * 2 + 1) * 16;
                ys[(mrA + g) * 33 + k] = yA0;
                ys[(mrA + g + 8) * 33 + k] = yB0;
                ys[(mrB + g) * 33 + k] = yA1;
                ys[(mrB + g + 8) * 33 + k] = yB1;
            }
        }
    }
    __syncthreads();

    // residual (re-read g_h from L2) + coalesced store
#pragma unroll
    for (int p = 0; p < 8; ++p) {
        const int idx = tid + p * 256;
        const int r = idx >> 3, c = (idx & 7) * 4;
        const float4 hv = *reinterpret_cast<const float4*>(
            &g_h[(size_t)(tok0 + r) * 512 + head * 32 + c]);
        float4 v;
        v.x = ys[r * 33 + c + 0] + hv.x;
        v.y = ys[r * 33 + c + 1] + hv.y;
        v.z = ys[r * 33 + c + 2] + hv.z;
        v.w = ys[r * 33 + c + 3] + hv.w;
        *reinterpret_cast<float4*>(
            &g_y[(size_t)(tok0 + r) * 512 + head * 32 + c]) = v;
    }
}

// ---------------------------------------------------------------------------
// K4: LayerNorm
// ---------------------------------------------------------------------------
__global__ __launch_bounds__(256) void ln_kernel(const float* __restrict__ gamma,
                                                 const float* __restrict__ beta,
                                                 float* __restrict__ out) {
    const int w = threadIdx.x >> 5, lane = threadIdx.x & 31;
    const int token = blockIdx.x * 8 + w;
    const float* yp = g_y + (size_t)token * En;
    float vals[16], sum = 0.f, sq = 0.f;
#pragma unroll
    for (int c2 = 0; c2 < 16; ++c2) {
        const float v = yp[c2 * 32 + lane];
        vals[c2] = v; sum += v; sq = fmaf(v, v, sq);
    }
#pragma unroll
    for (int o = 16; o; o >>= 1) {
        sum += __shfl_xor_sync(0xffffffffu, sum, o);
        sq += __shfl_xor_sync(0xffffffffu, sq, o);
    }
    const float mu = sum * (1.f / 512.f);
    const float var = sq * (1.f / 512.f) - mu * mu;
    const float inv = rsqrtf(var + LN_EPS);
    float* op = out + (size_t)token * En;
#pragma unroll
    for (int c2 = 0; c2 < 16; ++c2) {
        const int e = c2 * 32 + lane;
        op[e] = (vals[c2] - mu) * inv * gamma[e] + beta[e];
    }
}

// ---------------------------------------------------------------------------
extern "C" void kernel_launch(void* const* d_in, const int* in_sizes, int n_in,
                              void* d_out, int out_size) {
    const float* x = (const float*)d_in[0];
    const float* W = (const float*)d_in[1];
    const float* bias = (const float*)d_in[2];
    const float* cmap = (const float*)d_in[3];
    const float* gamma = (const float*)d_in[4];
    const float* beta = (const float*)d_in[5];
    float* out = (float*)d_out;

    static int smem_set = 0;
    if (!smem_set) {
        cudaFuncSetAttribute(bilinear_mma_kernel,
                             cudaFuncAttributeMaxDynamicSharedMemorySize, SM_TOTAL);
        cudaFuncSetAttribute(gemm_mma_kernel,
                             cudaFuncAttributeMaxDynamicSharedMemorySize, G_TOTAL);
        smem_set = 1;
    }

    cpack_kernel<<<64, 256>>>(cmap);
    wpack_kernel<<<128, 256>>>(W);
    gemm_mma_kernel<<<dim3(4, 128), 256, G_TOTAL>>>(x, bias);
    scan_local_kernel<<<NCHUNK * NCH / 256, 256>>>();
    scan_emit_kernel<<<NCHUNK * NCH / 256, 256>>>();
    bilinear_mma_kernel<<<dim3(64, Hn), 256, SM_TOTAL>>>();
    ln_kernel<<<BT / 8, 256>>>(gamma, beta, out);
}